// round 6
// baseline (speedup 1.0000x reference)
#include <cuda_runtime.h>
#include <cuda_bf16.h>
#include <math.h>

#define BB 16
#define NN 4096
#define MM 32
#define CC 512
#define MUVAL (1.0f/4096.0f)
#define NROWS (BB*NN)      // 65536

// ---------------- device scratch (no allocations allowed) ----------------
__device__ float g_cost[BB*NN*MM];      // 8 MB
__device__ float g_Kmat[BB*NN*MM];      // 8 MB
__device__ float g_pinorm[BB*NN*MM];    // 8 MB
__device__ float g_u[BB*NN];
__device__ float g_v[BB*MM];
__device__ float g_nu[BB*MM];
__device__ float g_spart[BB*64*MM];     // per-(b,chunk) K^T u partials
__device__ float g_errpart[1024];
__device__ float g_otpart[2048];
__device__ float g_y2[BB*MM*CC];        // y @ W2
__device__ int   g_done;
__device__ unsigned g_bar_count;
__device__ unsigned g_bar_gen;

// ---------------- init ----------------
__global__ void initKernel() {
    int t = blockIdx.x * 256 + threadIdx.x;
    if (t < BB*NN) g_u[t] = 0.f;
    if (t < BB*MM) g_v[t] = 0.f;
    if (t == 0) { g_done = 0; g_bar_count = 0u; g_bar_gen = 0u; }
}

// ---------------- nu from score_map ----------------
__global__ void nuKernel(const float* __restrict__ score) {
    __shared__ int cnt[MM];
    int b = blockIdx.x, tid = threadIdx.x;
    if (tid < MM) cnt[tid] = 0;
    __syncthreads();
    const float* sb = score + (long)b * MM * NN;
    for (int p = tid; p < NN; p += 256) {
        float best = sb[p]; int bi = 0;
        #pragma unroll
        for (int k = 1; k < MM; ++k) {
            float v = sb[k*NN + p];
            if (v > best) { best = v; bi = k; }
        }
        atomicAdd(&cnt[bi], 1);
    }
    __syncthreads();
    if (tid < MM) {
        float t0 = (float)cnt[tid] / ((float)NN + 1e-8f) + 1e-6f;
        float s = t0;
        #pragma unroll
        for (int o = 16; o; o >>= 1) s += __shfl_xor_sync(0xffffffffu, s, o);
        g_nu[b*MM + tid] = t0 / s;
    }
}

// ---------------- cost + K matrix ----------------
// grid 1024 = 16 batches x 64 row-blocks(64 rows). 256 threads. y tiled 16 rows.
__global__ void __launch_bounds__(256) costKernel(const float* __restrict__ x,
                                                  const float* __restrict__ y) {
    __shared__ float y_sm[16*CC];    // 32 KB
    __shared__ float yinv_sm[MM];
    int tid = threadIdx.x, lane = tid & 31, wid = tid >> 5;
    int b = blockIdx.x >> 6, rb = blockIdx.x & 63;
    const float* yb = y + (long)b * MM * CC;

    // y inverse norms: 8 warps x 4 m
    #pragma unroll
    for (int q = 0; q < 4; ++q) {
        int m = wid*4 + q;
        float ss = 0.f;
        #pragma unroll
        for (int j = 0; j < 16; ++j) { float vv = yb[m*CC + lane + j*32]; ss += vv*vv; }
        #pragma unroll
        for (int o = 16; o; o >>= 1) ss += __shfl_xor_sync(0xffffffffu, ss, o);
        if (lane == 0) yinv_sm[m] = rsqrtf(ss);
    }

    float dmine[8];
    #pragma unroll
    for (int r = 0; r < 8; ++r) dmine[r] = 0.f;

    for (int mh = 0; mh < 2; ++mh) {
        __syncthreads();
        // load y rows [mh*16, mh*16+16)
        for (int i = tid; i < 16*CC/4; i += 256)
            ((float4*)y_sm)[i] = ((const float4*)(yb + mh*16*CC))[i];
        __syncthreads();

        for (int r = 0; r < 8; ++r) {
            int n = rb*64 + wid*8 + r;
            const float4* xr = (const float4*)(x + ((long)b*NN + n) * CC);
            float4 xf[4];
            #pragma unroll
            for (int j = 0; j < 4; ++j) xf[j] = xr[lane + j*32];
            float ss = 0.f;
            #pragma unroll
            for (int j = 0; j < 4; ++j)
                ss += xf[j].x*xf[j].x + xf[j].y*xf[j].y + xf[j].z*xf[j].z + xf[j].w*xf[j].w;
            #pragma unroll
            for (int o = 16; o; o >>= 1) ss += __shfl_xor_sync(0xffffffffu, ss, o);
            float xinv = rsqrtf(ss);

            #pragma unroll 4
            for (int ml = 0; ml < 16; ++ml) {
                int m = mh*16 + ml;
                const float4* yr = (const float4*)(y_sm + ml*CC);
                float d = 0.f;
                #pragma unroll
                for (int j = 0; j < 4; ++j) {
                    float4 yv = yr[lane + j*32];
                    d += xf[j].x*yv.x + xf[j].y*yv.y + xf[j].z*yv.z + xf[j].w*yv.w;
                }
                #pragma unroll
                for (int o = 16; o; o >>= 1) d += __shfl_xor_sync(0xffffffffu, d, o);
                if (lane == m) dmine[r] = d * xinv;
            }
        }
    }
    __syncthreads();
    #pragma unroll
    for (int r = 0; r < 8; ++r) {
        int n = rb*64 + wid*8 + r;
        float c = 1.f - dmine[r] * yinv_sm[lane];
        long idx = ((long)b*NN + n) * MM + lane;
        g_cost[idx] = c;
        g_Kmat[idx] = expf(-c * 20.0f);
    }
}

// ---------------- sinkhorn: persistent kernel, 128 blocks, grid barrier ----------------
__device__ __forceinline__ void gbar() {
    __syncthreads();
    if (threadIdx.x == 0) {
        __threadfence();
        unsigned my = *(volatile unsigned*)&g_bar_gen;
        if (atomicAdd(&g_bar_count, 1u) == 127u) {
            atomicExch(&g_bar_count, 0u);
            __threadfence();
            atomicAdd(&g_bar_gen, 1u);
        } else {
            while (*(volatile unsigned*)&g_bar_gen == my) { __nanosleep(64); }
        }
        __threadfence();
    }
    __syncthreads();
}

__global__ void __launch_bounds__(256) sinkhornKernel() {
    int tid = threadIdx.x, lane = tid & 31, wid = tid >> 5;
    int gw = blockIdx.x * 8 + wid;           // 0..1023
    int b = gw >> 6, chunk = gw & 63;        // 64 row-chunks of 64 per batch

    for (int it = 0; it < 50; ++it) {
        if (*(volatile int*)&g_done) break;

        // Phase A: u update + K^T u partials + err partials
        float acc = 0.f, errs = 0.f;
        float vv = g_v[b*MM + lane];
        for (int r = 0; r < 64; ++r) {
            int n = chunk*64 + r;
            long idx = ((long)b*NN + n) * MM + lane;
            float Kx = g_Kmat[idx];
            float s = Kx * vv;
            #pragma unroll
            for (int o = 16; o; o >>= 1) s += __shfl_xor_sync(0xffffffffu, s, o);
            float un = MUVAL / (s + 1e-8f);
            acc += Kx * un;
            if (lane == 0) {
                errs += fabsf(un - g_u[b*NN + n]);
                g_u[b*NN + n] = un;
            }
        }
        g_spart[gw*MM + lane] = acc;
        if (lane == 0) g_errpart[gw] = errs;
        gbar();

        // Phase B: v update (warps 0..511) + err check (warp 1023)
        if (gw < 512) {
            int bb = gw >> 5, m = gw & 31;
            float s = g_spart[(bb*64 + lane)*MM + m] + g_spart[(bb*64 + 32 + lane)*MM + m];
            #pragma unroll
            for (int o = 16; o; o >>= 1) s += __shfl_xor_sync(0xffffffffu, s, o);
            if (lane == 0) g_v[bb*MM + m] = g_nu[bb*MM + m] / (s + 1e-8f);
        }
        if (gw == 1023) {
            float e = 0.f;
            for (int j = lane; j < 1024; j += 32) e += g_errpart[j];
            #pragma unroll
            for (int o = 16; o; o >>= 1) e += __shfl_xor_sync(0xffffffffu, e, o);
            if (lane == 0 && (e / (float)BB) < 0.1f) {
                *(volatile int*)&g_done = 1;
                __threadfence();
            }
        }
        gbar();
    }
}

// ---------------- Y2 = y @ W2 : 16 blocks ----------------
__global__ void __launch_bounds__(256) y2Kernel(const float* __restrict__ y,
                                                const float* __restrict__ W) {
    __shared__ float ys[MM*64];   // 8 KB
    int b = blockIdx.x, tid = threadIdx.x;
    const float* W2 = W + 512*512;
    const float* yb = y + (long)b * MM * CC;
    float acc0[MM], acc1[MM];
    #pragma unroll
    for (int m = 0; m < MM; ++m) { acc0[m] = 0.f; acc1[m] = 0.f; }

    for (int kc = 0; kc < CC; kc += 64) {
        __syncthreads();
        for (int i = tid; i < MM*64/4; i += 256) {
            int m = i >> 4, k4 = (i & 15) * 4;
            ((float4*)(ys + m*64))[k4>>2] = *(const float4*)(yb + m*CC + kc + k4);
        }
        __syncthreads();
        for (int k = 0; k < 64; ++k) {
            float w0 = W2[(long)(kc + k)*CC + tid];
            float w1 = W2[(long)(kc + k)*CC + tid + 256];
            #pragma unroll
            for (int m = 0; m < MM; ++m) {
                float yv = ys[m*64 + k];
                acc0[m] += yv * w0;
                acc1[m] += yv * w1;
            }
        }
    }
    #pragma unroll
    for (int m = 0; m < MM; ++m) {
        g_y2[((long)b*MM + m)*CC + tid]       = acc0[m];
        g_y2[((long)b*MM + m)*CC + tid + 256] = acc1[m];
    }
}

// ---------------- pi, pi_norm, ot partials ----------------
__global__ void __launch_bounds__(256) piKernel(float* __restrict__ d_pi, int write_pi) {
    int tid = threadIdx.x, lane = tid & 31, wid = tid >> 5;
    int gw = blockIdx.x * 8 + wid;           // 0..2047
    int b = gw >> 7, sub = gw & 127;         // 32 rows per warp
    float vv = g_v[b*MM + lane];
    float ot = 0.f;
    for (int r = 0; r < 32; ++r) {
        int n = sub*32 + r;
        long idx = ((long)b*NN + n) * MM + lane;
        float pi = g_u[b*NN + n] * g_Kmat[idx] * vv;
        float rs = pi;
        #pragma unroll
        for (int o = 16; o; o >>= 1) rs += __shfl_xor_sync(0xffffffffu, rs, o);
        g_pinorm[idx] = pi / (rs + 1e-8f);
        if (write_pi) d_pi[idx] = pi;
        ot += pi * g_cost[idx];
    }
    #pragma unroll
    for (int o = 16; o; o >>= 1) ot += __shfl_xor_sync(0xffffffffu, ot, o);
    if (lane == 0) g_otpart[gw] = ot;
}

__global__ void otReduceKernel(float* __restrict__ d_ot) {
    int lane = threadIdx.x & 31, b = threadIdx.x >> 5;   // 512 threads -> 16 warps
    float s = g_otpart[b*128 + lane] + g_otpart[b*128 + lane + 32]
            + g_otpart[b*128 + lane + 64] + g_otpart[b*128 + lane + 96];
    #pragma unroll
    for (int o = 16; o; o >>= 1) s += __shfl_xor_sync(0xffffffffu, s, o);
    if (lane == 0) d_ot[b] = s;
}

// ---------------- main GEMM: out = x@W1 + pinorm@Y2 + bias (pre-LN) ----------------
// 2048 blocks = 512 row-tiles x 4 col-tiles. 256 threads, 8x8 micro.
__global__ void __launch_bounds__(256) gemmKernel(const float* __restrict__ x,
                                                  const float* __restrict__ W,
                                                  const float* __restrict__ bias,
                                                  float* __restrict__ out) {
    __shared__ float As[8][128];
    __shared__ float Bs[8][128];
    int tid = threadIdx.x;
    int tx = tid & 15, ty = tid >> 4;
    int rowTile = blockIdx.x >> 2, colTile = blockIdx.x & 3;
    int row0 = rowTile * 128;
    int b = row0 >> 12;
    int c0 = colTile * 128;

    int ar = tid >> 1;               // 0..127
    int ak = (tid & 1) * 4;          // 0 or 4
    int bk = tid >> 5;               // 0..7
    int bc = (tid & 31) * 4;

    float acc[8][8];
    #pragma unroll
    for (int i = 0; i < 8; ++i)
        #pragma unroll
        for (int j = 0; j < 8; ++j) acc[i][j] = 0.f;

    const float* xbase = x + (long)(row0 + ar) * CC;

    // main K=512 over x / W1
    for (int k0 = 0; k0 < CC; k0 += 8) {
        float4 av = *(const float4*)(xbase + k0 + ak);
        float4 bv = *(const float4*)(W + (long)(k0 + bk)*CC + c0 + bc);
        __syncthreads();
        As[ak+0][ar] = av.x; As[ak+1][ar] = av.y; As[ak+2][ar] = av.z; As[ak+3][ar] = av.w;
        *(float4*)&Bs[bk][bc] = bv;
        __syncthreads();
        #pragma unroll
        for (int kk = 0; kk < 8; ++kk) {
            float4 a0 = *(float4*)&As[kk][ty*8];
            float4 a1 = *(float4*)&As[kk][ty*8 + 4];
            float4 b0 = *(float4*)&Bs[kk][tx*8];
            float4 b1 = *(float4*)&Bs[kk][tx*8 + 4];
            float a[8] = {a0.x,a0.y,a0.z,a0.w,a1.x,a1.y,a1.z,a1.w};
            float bb2[8] = {b0.x,b0.y,b0.z,b0.w,b1.x,b1.y,b1.z,b1.w};
            #pragma unroll
            for (int i = 0; i < 8; ++i)
                #pragma unroll
                for (int j = 0; j < 8; ++j) acc[i][j] += a[i]*bb2[j];
        }
    }

    // K=32 tail: pinorm / Y2[b]
    const float* pbase = g_pinorm + (long)(row0 + ar) * MM;
    for (int k0 = 0; k0 < MM; k0 += 8) {
        float4 av = *(const float4*)(pbase + k0 + ak);
        float4 bv = *(const float4*)(g_y2 + ((long)b*MM + k0 + bk)*CC + c0 + bc);
        __syncthreads();
        As[ak+0][ar] = av.x; As[ak+1][ar] = av.y; As[ak+2][ar] = av.z; As[ak+3][ar] = av.w;
        *(float4*)&Bs[bk][bc] = bv;
        __syncthreads();
        #pragma unroll
        for (int kk = 0; kk < 8; ++kk) {
            float4 a0 = *(float4*)&As[kk][ty*8];
            float4 a1 = *(float4*)&As[kk][ty*8 + 4];
            float4 b0 = *(float4*)&Bs[kk][tx*8];
            float4 b1 = *(float4*)&Bs[kk][tx*8 + 4];
            float a[8] = {a0.x,a0.y,a0.z,a0.w,a1.x,a1.y,a1.z,a1.w};
            float bb2[8] = {b0.x,b0.y,b0.z,b0.w,b1.x,b1.y,b1.z,b1.w};
            #pragma unroll
            for (int i = 0; i < 8; ++i)
                #pragma unroll
                for (int j = 0; j < 8; ++j) acc[i][j] += a[i]*bb2[j];
        }
    }

    // epilogue: + bias, write pre-LN
    #pragma unroll
    for (int i = 0; i < 8; ++i) {
        long orow = row0 + ty*8 + i;
        int cbase = c0 + tx*8;
        float4 o0, o1;
        o0.x = acc[i][0] + bias[cbase+0]; o0.y = acc[i][1] + bias[cbase+1];
        o0.z = acc[i][2] + bias[cbase+2]; o0.w = acc[i][3] + bias[cbase+3];
        o1.x = acc[i][4] + bias[cbase+4]; o1.y = acc[i][5] + bias[cbase+5];
        o1.z = acc[i][6] + bias[cbase+6]; o1.w = acc[i][7] + bias[cbase+7];
        *(float4*)(out + orow*CC + cbase)     = o0;
        *(float4*)(out + orow*CC + cbase + 4) = o1;
    }
}

// ---------------- LayerNorm in-place, warp per row ----------------
__global__ void __launch_bounds__(256) lnKernel(float* __restrict__ out,
                                                const float* __restrict__ gamma,
                                                const float* __restrict__ beta) {
    int tid = threadIdx.x, lane = tid & 31, wid = tid >> 5;
    long row = (long)blockIdx.x * 8 + wid;   // grid 8192 -> 65536 rows
    float4* rp = (float4*)(out + row * CC);
    float4 v[4];
    float sum = 0.f;
    #pragma unroll
    for (int j = 0; j < 4; ++j) {
        v[j] = rp[lane + j*32];
        sum += v[j].x + v[j].y + v[j].z + v[j].w;
    }
    #pragma unroll
    for (int o = 16; o; o >>= 1) sum += __shfl_xor_sync(0xffffffffu, sum, o);
    float mean = sum * (1.0f/512.0f);
    float var = 0.f;
    #pragma unroll
    for (int j = 0; j < 4; ++j) {
        float dx = v[j].x - mean, dy = v[j].y - mean, dz = v[j].z - mean, dw = v[j].w - mean;
        var += dx*dx + dy*dy + dz*dz + dw*dw;
    }
    #pragma unroll
    for (int o = 16; o; o >>= 1) var += __shfl_xor_sync(0xffffffffu, var, o);
    float rs = rsqrtf(var * (1.0f/512.0f) + 1e-5f);
    const float4* g4 = (const float4*)gamma;
    const float4* b4 = (const float4*)beta;
    #pragma unroll
    for (int j = 0; j < 4; ++j) {
        float4 g = g4[lane + j*32], bt = b4[lane + j*32];
        float4 o;
        o.x = (v[j].x - mean)*rs*g.x + bt.x;
        o.y = (v[j].y - mean)*rs*g.y + bt.y;
        o.z = (v[j].z - mean)*rs*g.z + bt.z;
        o.w = (v[j].w - mean)*rs*g.w + bt.w;
        rp[lane + j*32] = o;
    }
}

// ---------------- launch ----------------
extern "C" void kernel_launch(void* const* d_in, const int* in_sizes, int n_in,
                              void* d_out, int out_size) {
    const float* x     = (const float*)d_in[0];   // source_feat [16,4096,512]
    const float* y     = (const float*)d_in[1];   // target_feat_matrix [16,32,512]
    const float* score = (const float*)d_in[2];   // score_map [16,32,64,64]
    const float* W     = (const float*)d_in[3];   // fusion_w [1024,512]
    const float* bias  = (const float*)d_in[4];   // fusion_b [512]
    const float* gamma = (const float*)d_in[5];   // ln_gamma [512]
    const float* beta  = (const float*)d_in[6];   // ln_beta [512]
    float* out = (float*)d_out;

    const long OUT_ELEMS = (long)BB*NN*CC;        // 33554432
    int full = (out_size >= (int)(OUT_ELEMS + BB + (long)BB*NN*MM));
    float* d_ot = full ? out + OUT_ELEMS : nullptr;
    float* d_pi = full ? out + OUT_ELEMS + BB : nullptr;

    initKernel<<<256, 256>>>();
    nuKernel<<<BB, 256>>>(score);
    costKernel<<<1024, 256>>>(x, y);
    sinkhornKernel<<<128, 256>>>();
    y2Kernel<<<BB, 256>>>(y, W);
    piKernel<<<256, 256>>>(d_pi, full);
    if (full) otReduceKernel<<<1, 512>>>(d_ot);
    gemmKernel<<<2048, 256>>>(x, W, bias, out);
    lnKernel<<<8192, 256>>>(out, gamma, beta);
}

// round 7
// speedup vs baseline: 3.9766x; 3.9766x over previous
#include <cuda_runtime.h>
#include <cuda_bf16.h>
#include <math.h>

#define BB 16
#define NN 4096
#define MM 32
#define CC 512
#define MUVAL (1.0f/4096.0f)
#define SINK_BLOCKS 256

// ---------------- device scratch (no allocations allowed) ----------------
__device__ float g_cost[BB*NN*MM];      // 8 MB
__device__ float g_Kmat[BB*NN*MM];      // 8 MB
__device__ float g_pinorm[BB*NN*MM];    // 8 MB
__device__ float g_u[BB*NN];
__device__ float g_v[BB*MM];
__device__ float g_nu[BB*MM];
__device__ float g_spart[2048*MM];
__device__ float g_errpart[2048];
__device__ float g_otpart[2048];
__device__ float g_y2[BB*MM*CC];
__device__ int   g_done;
__device__ unsigned g_bar_count;
__device__ unsigned g_bar_gen;

// ---------------- f32x2 helpers ----------------
__device__ __forceinline__ void fma2(unsigned long long& d, unsigned long long a, unsigned long long b) {
    asm("fma.rn.f32x2 %0, %1, %2, %0;" : "+l"(d) : "l"(a), "l"(b));
}
__device__ __forceinline__ unsigned long long pack2(float x) {
    unsigned long long r; unsigned u = __float_as_uint(x);
    asm("mov.b64 %0, {%1, %1};" : "=l"(r) : "r"(u));
    return r;
}
__device__ __forceinline__ float f2lo(unsigned long long v) { return __uint_as_float((unsigned)v); }
__device__ __forceinline__ float f2hi(unsigned long long v) { return __uint_as_float((unsigned)(v >> 32)); }

// ---------------- init ----------------
__global__ void initKernel() {
    int t = threadIdx.x;
    if (t < BB*MM) g_v[t] = 0.f;
    if (t == 0) { g_done = 0; g_bar_count = 0u; g_bar_gen = 0u; }
}

// ---------------- nu from score_map ----------------
__global__ void nuKernel(const float* __restrict__ score) {
    __shared__ int cnt[MM];
    int b = blockIdx.x, tid = threadIdx.x;
    if (tid < MM) cnt[tid] = 0;
    __syncthreads();
    const float* sb = score + (long)b * MM * NN;
    for (int p = tid; p < NN; p += 256) {
        float best = sb[p]; int bi = 0;
        #pragma unroll
        for (int k = 1; k < MM; ++k) {
            float v = sb[k*NN + p];
            if (v > best) { best = v; bi = k; }
        }
        atomicAdd(&cnt[bi], 1);
    }
    __syncthreads();
    if (tid < MM) {
        float t0 = (float)cnt[tid] / ((float)NN + 1e-8f) + 1e-6f;
        float s = t0;
        #pragma unroll
        for (int o = 16; o; o >>= 1) s += __shfl_xor_sync(0xffffffffu, s, o);
        g_nu[b*MM + tid] = t0 / s;
    }
}

// ---------------- cost + K : register-tiled, no shuffles ----------------
// 512 blocks = 16 b x 32 row-blocks(128 rows). 256 thr: tx=m(32), ty=rowgrp(8)x16rows
__global__ void __launch_bounds__(256) costKernel(const float* __restrict__ x,
                                                  const float* __restrict__ y) {
    __shared__ float xs[128*33];     // padded rows of 33
    __shared__ float ys[32*33];
    __shared__ float xinvs[128];
    __shared__ float yinvs[32];
    int tid = threadIdx.x, tx = tid & 31, ty = tid >> 5;
    int b = blockIdx.x >> 5, rb = blockIdx.x & 31;
    int row0 = rb * 128;

    float acc[16];
    #pragma unroll
    for (int i = 0; i < 16; ++i) acc[i] = 0.f;
    float xn = 0.f, yn = 0.f;

    for (int kc = 0; kc < CC; kc += 32) {
        __syncthreads();
        // x chunk: 128 rows x 32 k
        #pragma unroll
        for (int pass = 0; pass < 4; ++pass) {
            int r = pass*32 + (tid >> 3);
            int kk = (tid & 7) * 4;
            float4 v = *(const float4*)(x + ((long)b*NN + row0 + r)*CC + kc + kk);
            xs[r*33 + kk]   = v.x; xs[r*33 + kk+1] = v.y;
            xs[r*33 + kk+2] = v.z; xs[r*33 + kk+3] = v.w;
        }
        // y chunk: 32 m x 32 k
        {
            int m = tid >> 3, kk = (tid & 7) * 4;
            float4 v = *(const float4*)(y + ((long)b*MM + m)*CC + kc + kk);
            ys[m*33 + kk]   = v.x; ys[m*33 + kk+1] = v.y;
            ys[m*33 + kk+2] = v.z; ys[m*33 + kk+3] = v.w;
        }
        __syncthreads();
        if (tid < 128) {
            #pragma unroll
            for (int k = 0; k < 32; ++k) { float v = xs[tid*33 + k]; xn += v*v; }
        }
        if (tid < 32) {
            #pragma unroll
            for (int k = 0; k < 32; ++k) { float v = ys[tid*33 + k]; yn += v*v; }
        }
        #pragma unroll 4
        for (int k = 0; k < 32; ++k) {
            float bv = ys[tx*33 + k];
            #pragma unroll
            for (int i = 0; i < 16; ++i)
                acc[i] += xs[(ty*16 + i)*33 + k] * bv;
        }
    }
    if (tid < 128) xinvs[tid] = rsqrtf(xn);
    if (tid < 32)  yinvs[tid] = rsqrtf(yn);
    __syncthreads();
    float yi = yinvs[tx];
    #pragma unroll
    for (int i = 0; i < 16; ++i) {
        int r = ty*16 + i;
        float c = 1.f - acc[i] * xinvs[r] * yi;
        long idx = ((long)b*NN + row0 + r) * MM + tx;
        g_cost[idx] = c;
        g_Kmat[idx] = expf(-c * 20.0f);
    }
}

// ---------------- sinkhorn: persistent, K cached in smem, 256 blocks ----------------
__device__ __forceinline__ void gbar() {
    __threadfence();
    __syncthreads();
    if (threadIdx.x == 0) {
        unsigned my = *(volatile unsigned*)&g_bar_gen;
        if (atomicAdd(&g_bar_count, 1u) == (SINK_BLOCKS - 1u)) {
            atomicExch(&g_bar_count, 0u);
            __threadfence();
            atomicAdd(&g_bar_gen, 1u);
        } else {
            while (*(volatile unsigned*)&g_bar_gen == my) { __nanosleep(64); }
        }
        __threadfence();
    }
    __syncthreads();
}

__global__ void __launch_bounds__(256) sinkhornKernel() {
    __shared__ float ks[8 * 32 * 33];      // 33.8 KB
    int tid = threadIdx.x, lane = tid & 31, wid = tid >> 5;
    int gw = blockIdx.x * 8 + wid;          // 0..2047
    int b = gw >> 7, chunk = gw & 127;      // 128 chunks of 32 rows per batch
    long rowbase = (long)b*NN + chunk*32;
    float* kw = ks + wid * (32*33);

    // cache this warp's K tile: 32 rows x 32 m, pad 33
    for (int r = 0; r < 32; ++r)
        kw[r*33 + lane] = g_Kmat[(rowbase + r)*MM + lane];
    __syncwarp();

    float uprev = 0.f;
    for (int it = 0; it < 50; ++it) {
        if (*(volatile int*)&g_done) break;

        float vreg = __ldcg(&g_v[b*MM + lane]);
        // s_row (row = lane) = sum_m K[row][m] * v[m]
        float s = 0.f;
        #pragma unroll
        for (int m = 0; m < 32; ++m)
            s += kw[lane*33 + m] * __shfl_sync(0xffffffffu, vreg, m);
        float un = MUVAL / (s + 1e-8f);
        float errl = fabsf(un - uprev);
        uprev = un;
        // (K^T u)[m] partial for m = lane over this warp's 32 rows
        float acc = 0.f;
        #pragma unroll
        for (int j = 0; j < 32; ++j)
            acc += kw[j*33 + lane] * __shfl_sync(0xffffffffu, un, j);
        __stcg(&g_spart[gw*MM + lane], acc);
        #pragma unroll
        for (int o = 16; o; o >>= 1) errl += __shfl_xor_sync(0xffffffffu, errl, o);
        if (lane == 0) __stcg(&g_errpart[gw], errl);
        gbar();

        if (gw < 512) {   // v update: warp per (b, m-half)... (bb = gw>>5, m = gw&31)
            int bb = gw >> 5, m = gw & 31;
            float ss = 0.f;
            #pragma unroll
            for (int j = 0; j < 4; ++j)
                ss += __ldcg(&g_spart[((long)bb*128 + lane + 32*j)*MM + m]);
            #pragma unroll
            for (int o = 16; o; o >>= 1) ss += __shfl_xor_sync(0xffffffffu, ss, o);
            if (lane == 0) __stcg(&g_v[bb*MM + m], g_nu[bb*MM + m] / (ss + 1e-8f));
        }
        if (gw == 2047) { // global err check
            float e = 0.f;
            for (int j = lane; j < 2048; j += 32) e += __ldcg(&g_errpart[j]);
            #pragma unroll
            for (int o = 16; o; o >>= 1) e += __shfl_xor_sync(0xffffffffu, e, o);
            if (lane == 0 && (e / (float)BB) < 0.1f) {
                *(volatile int*)&g_done = 1;
                __threadfence();
            }
        }
        gbar();
    }
    g_u[rowbase + lane] = uprev;
}

// ---------------- Y2 = y @ W2 : 64 blocks ----------------
__global__ void __launch_bounds__(256) y2Kernel(const float* __restrict__ y,
                                                const float* __restrict__ W) {
    __shared__ float ys[MM][64];
    int tid = threadIdx.x;
    int b = blockIdx.x >> 2, c0 = (blockIdx.x & 3) * 128;
    int col = c0 + (tid & 127), mh = tid >> 7;
    const float* W2 = W + 512*512;
    float acc[16];
    #pragma unroll
    for (int i = 0; i < 16; ++i) acc[i] = 0.f;

    for (int kc = 0; kc < CC; kc += 64) {
        __syncthreads();
        {
            int m = tid >> 3, k4 = (tid & 7) * 8;
            float4 v0 = *(const float4*)(y + ((long)b*MM + m)*CC + kc + k4);
            float4 v1 = *(const float4*)(y + ((long)b*MM + m)*CC + kc + k4 + 4);
            *(float4*)&ys[m][k4]     = v0;
            *(float4*)&ys[m][k4 + 4] = v1;
        }
        __syncthreads();
        #pragma unroll 4
        for (int k = 0; k < 64; ++k) {
            float w = W2[(long)(kc + k)*CC + col];
            #pragma unroll
            for (int i = 0; i < 16; ++i) acc[i] += ys[mh*16 + i][k] * w;
        }
    }
    #pragma unroll
    for (int i = 0; i < 16; ++i)
        g_y2[((long)b*MM + mh*16 + i)*CC + col] = acc[i];
}

// ---------------- pi, pi_norm, ot partials ----------------
__global__ void __launch_bounds__(256) piKernel(float* __restrict__ d_pi, int write_pi) {
    int tid = threadIdx.x, lane = tid & 31, wid = tid >> 5;
    int gw = blockIdx.x * 8 + wid;           // 0..2047
    int b = gw >> 7, sub = gw & 127;
    float vv = g_v[b*MM + lane];
    float ot = 0.f;
    for (int r = 0; r < 32; ++r) {
        int n = sub*32 + r;
        long idx = ((long)b*NN + n) * MM + lane;
        float pi = g_u[b*NN + n] * g_Kmat[idx] * vv;
        float rs = pi;
        #pragma unroll
        for (int o = 16; o; o >>= 1) rs += __shfl_xor_sync(0xffffffffu, rs, o);
        g_pinorm[idx] = pi / (rs + 1e-8f);
        if (write_pi) d_pi[idx] = pi;
        ot += pi * g_cost[idx];
    }
    #pragma unroll
    for (int o = 16; o; o >>= 1) ot += __shfl_xor_sync(0xffffffffu, ot, o);
    if (lane == 0) g_otpart[gw] = ot;
}

__global__ void otReduceKernel(float* __restrict__ d_ot) {
    int lane = threadIdx.x & 31, b = threadIdx.x >> 5;
    float s = g_otpart[b*128 + lane] + g_otpart[b*128 + lane + 32]
            + g_otpart[b*128 + lane + 64] + g_otpart[b*128 + lane + 96];
    #pragma unroll
    for (int o = 16; o; o >>= 1) s += __shfl_xor_sync(0xffffffffu, s, o);
    if (lane == 0) d_ot[b] = s;
}

// ---------------- main GEMM: out = x@W1 + pinorm@Y2[b] + bias (pre-LN) ----------------
// 2048 blocks = 512 rowTiles x 4 colTiles. 256 thr, 8x8 micro via fma.rn.f32x2,
// double-buffered K=16 chunks (32 for X/W1 + 2 for P/Y2).
__global__ void __launch_bounds__(256, 2) gemmKernel(const float* __restrict__ x,
                                                     const float* __restrict__ W,
                                                     const float* __restrict__ bias,
                                                     float* __restrict__ out) {
    __shared__ float As[2][16*128];
    __shared__ float Bs[2][16*128];
    int tid = threadIdx.x;
    int tx = tid & 15, ty = tid >> 4;
    int rowTile = blockIdx.x >> 2, colTile = blockIdx.x & 3;
    int row0 = rowTile * 128, c0 = colTile * 128;
    int b = row0 >> 12;
    int ar = tid >> 1, ak = (tid & 1) * 8;
    int bk = tid >> 4, bc = (tid & 15) * 4;

    unsigned long long acc[8][4];
    #pragma unroll
    for (int i = 0; i < 8; ++i)
        #pragma unroll
        for (int j = 0; j < 4; ++j) acc[i][j] = 0ull;

    const float* xrow = x + (long)(row0 + ar) * CC;
    const float* prow = g_pinorm + (long)(row0 + ar) * MM;
    const float* y2b  = g_y2 + (long)b * MM * CC;

    float4 av0, av1, bv0, bv1;
    // prologue: chunk 0
    av0 = *(const float4*)(xrow + ak);
    av1 = *(const float4*)(xrow + ak + 4);
    bv0 = *(const float4*)(W + (long)bk*CC + c0 + bc);
    bv1 = *(const float4*)(W + (long)bk*CC + c0 + bc + 64);
    {
        float* Ad = As[0]; float* Bd = Bs[0];
        Ad[(ak+0)*128+ar]=av0.x; Ad[(ak+1)*128+ar]=av0.y; Ad[(ak+2)*128+ar]=av0.z; Ad[(ak+3)*128+ar]=av0.w;
        Ad[(ak+4)*128+ar]=av1.x; Ad[(ak+5)*128+ar]=av1.y; Ad[(ak+6)*128+ar]=av1.z; Ad[(ak+7)*128+ar]=av1.w;
        *(float4*)(Bd + bk*128 + bc)      = bv0;
        *(float4*)(Bd + bk*128 + bc + 64) = bv1;
    }
    __syncthreads();

    for (int cc = 0; cc < 34; ++cc) {
        int buf = cc & 1;
        if (cc < 33) {
            int nc = cc + 1;
            if (nc < 32) {
                av0 = *(const float4*)(xrow + nc*16 + ak);
                av1 = *(const float4*)(xrow + nc*16 + ak + 4);
                bv0 = *(const float4*)(W + (long)(nc*16 + bk)*CC + c0 + bc);
                bv1 = *(const float4*)(W + (long)(nc*16 + bk)*CC + c0 + bc + 64);
            } else {
                int t = (nc - 32) * 16;
                av0 = *(const float4*)(prow + t + ak);
                av1 = *(const float4*)(prow + t + ak + 4);
                bv0 = *(const float4*)(y2b + (long)(t + bk)*CC + c0 + bc);
                bv1 = *(const float4*)(y2b + (long)(t + bk)*CC + c0 + bc + 64);
            }
        }
        const float* Ab = As[buf];
        const float* Bb = Bs[buf];
        #pragma unroll
        for (int kk = 0; kk < 16; ++kk) {
            float4 a0 = *(const float4*)(Ab + kk*128 + ty*8);
            float4 a1 = *(const float4*)(Ab + kk*128 + ty*8 + 4);
            unsigned long long a2[8];
            a2[0]=pack2(a0.x); a2[1]=pack2(a0.y); a2[2]=pack2(a0.z); a2[3]=pack2(a0.w);
            a2[4]=pack2(a1.x); a2[5]=pack2(a1.y); a2[6]=pack2(a1.z); a2[7]=pack2(a1.w);
            const unsigned long long* bp  = (const unsigned long long*)(Bb + kk*128 + tx*4);
            const unsigned long long* bp2 = (const unsigned long long*)(Bb + kk*128 + tx*4 + 64);
            unsigned long long b2[4];
            b2[0]=bp[0]; b2[1]=bp[1]; b2[2]=bp2[0]; b2[3]=bp2[1];
            #pragma unroll
            for (int i = 0; i < 8; ++i)
                #pragma unroll
                for (int j = 0; j < 4; ++j)
                    fma2(acc[i][j], a2[i], b2[j]);
        }
        if (cc < 33) {
            __syncthreads();
            float* Ad = As[buf ^ 1]; float* Bd = Bs[buf ^ 1];
            Ad[(ak+0)*128+ar]=av0.x; Ad[(ak+1)*128+ar]=av0.y; Ad[(ak+2)*128+ar]=av0.z; Ad[(ak+3)*128+ar]=av0.w;
            Ad[(ak+4)*128+ar]=av1.x; Ad[(ak+5)*128+ar]=av1.y; Ad[(ak+6)*128+ar]=av1.z; Ad[(ak+7)*128+ar]=av1.w;
            *(float4*)(Bd + bk*128 + bc)      = bv0;
            *(float4*)(Bd + bk*128 + bc + 64) = bv1;
            __syncthreads();
        }
    }

    // epilogue: + bias, write pre-LN
    #pragma unroll
    for (int i = 0; i < 8; ++i) {
        long orow = row0 + ty*8 + i;
        int cA = c0 + tx*4, cB = cA + 64;
        float4 o;
        o.x = f2lo(acc[i][0]) + bias[cA+0];
        o.y = f2hi(acc[i][0]) + bias[cA+1];
        o.z = f2lo(acc[i][1]) + bias[cA+2];
        o.w = f2hi(acc[i][1]) + bias[cA+3];
        *(float4*)(out + orow*CC + cA) = o;
        o.x = f2lo(acc[i][2]) + bias[cB+0];
        o.y = f2hi(acc[i][2]) + bias[cB+1];
        o.z = f2lo(acc[i][3]) + bias[cB+2];
        o.w = f2hi(acc[i][3]) + bias[cB+3];
        *(float4*)(out + orow*CC + cB) = o;
    }
}

// ---------------- LayerNorm in-place, warp per row ----------------
__global__ void __launch_bounds__(256) lnKernel(float* __restrict__ out,
                                                const float* __restrict__ gamma,
                                                const float* __restrict__ beta) {
    int tid = threadIdx.x, lane = tid & 31, wid = tid >> 5;
    long row = (long)blockIdx.x * 8 + wid;
    float4* rp = (float4*)(out + row * CC);
    float4 v[4];
    float sum = 0.f;
    #pragma unroll
    for (int j = 0; j < 4; ++j) {
        v[j] = rp[lane + j*32];
        sum += v[j].x + v[j].y + v[j].z + v[j].w;
    }
    #pragma unroll
    for (int o = 16; o; o >>= 1) sum += __shfl_xor_sync(0xffffffffu, sum, o);
    float mean = sum * (1.0f/512.0f);
    float var = 0.f;
    #pragma unroll
    for (int j = 0; j < 4; ++j) {
        float dx = v[j].x - mean, dy = v[j].y - mean, dz = v[j].z - mean, dw = v[j].w - mean;
        var += dx*dx + dy*dy + dz*dz + dw*dw;
    }
    #pragma unroll
    for (int o = 16; o; o >>= 1) var += __shfl_xor_sync(0xffffffffu, var, o);
    float rs = rsqrtf(var * (1.0f/512.0f) + 1e-5f);
    const float4* g4 = (const float4*)gamma;
    const float4* b4 = (const float4*)beta;
    #pragma unroll
    for (int j = 0; j < 4; ++j) {
        float4 g = g4[lane + j*32], bt = b4[lane + j*32];
        float4 o;
        o.x = (v[j].x - mean)*rs*g.x + bt.x;
        o.y = (v[j].y - mean)*rs*g.y + bt.y;
        o.z = (v[j].z - mean)*rs*g.z + bt.z;
        o.w = (v[j].w - mean)*rs*g.w + bt.w;
        rp[lane + j*32] = o;
    }
}

// ---------------- launch ----------------
extern "C" void kernel_launch(void* const* d_in, const int* in_sizes, int n_in,
                              void* d_out, int out_size) {
    const float* x     = (const float*)d_in[0];
    const float* y     = (const float*)d_in[1];
    const float* score = (const float*)d_in[2];
    const float* W     = (const float*)d_in[3];
    const float* bias  = (const float*)d_in[4];
    const float* gamma = (const float*)d_in[5];
    const float* beta  = (const float*)d_in[6];
    float* out = (float*)d_out;

    const long OUT_ELEMS = (long)BB*NN*CC;
    int full = (out_size >= (int)(OUT_ELEMS + BB + (long)BB*NN*MM));
    float* d_ot = full ? out + OUT_ELEMS : nullptr;
    float* d_pi = full ? out + OUT_ELEMS + BB : nullptr;

    initKernel<<<1, 512>>>();
    nuKernel<<<BB, 256>>>(score);
    costKernel<<<512, 256>>>(x, y);
    sinkhornKernel<<<SINK_BLOCKS, 256>>>();
    y2Kernel<<<64, 256>>>(y, W);
    piKernel<<<256, 256>>>(d_pi, full);
    if (full) otReduceKernel<<<1, 512>>>(d_ot);
    gemmKernel<<<2048, 256>>>(x, W, bias, out);
    lnKernel<<<8192, 256>>>(out, gamma, beta);
}

// round 8
// speedup vs baseline: 3.9816x; 1.0013x over previous
#include <cuda_runtime.h>
#include <cuda_bf16.h>
#include <math.h>

#define BB 16
#define NN 4096
#define MM 32
#define CC 512
#define MUVAL (1.0f/4096.0f)
#define SINK_BLOCKS 256

// ---------------- device scratch (no allocations allowed) ----------------
__device__ float g_cost[BB*NN*MM];      // 8 MB
__device__ float g_Kmat[BB*NN*MM];      // 8 MB
__device__ float g_pinorm[BB*NN*MM];    // 8 MB
__device__ float g_u[BB*NN];
__device__ float g_v[BB*MM];
__device__ float g_nu[BB*MM];
__device__ float g_spart[2048*MM];
__device__ float g_errpart[2048];
__device__ float g_otpart[2048];
__device__ float g_y2[BB*MM*CC];
__device__ int   g_done;
__device__ unsigned g_bar_count;
__device__ unsigned g_bar_gen;

// ---------------- f32x2 helpers ----------------
__device__ __forceinline__ void fma2(unsigned long long& d, unsigned long long a, unsigned long long b) {
    asm("fma.rn.f32x2 %0, %1, %2, %0;" : "+l"(d) : "l"(a), "l"(b));
}
__device__ __forceinline__ unsigned long long pack2(float x) {
    unsigned long long r; unsigned u = __float_as_uint(x);
    asm("mov.b64 %0, {%1, %1};" : "=l"(r) : "r"(u));
    return r;
}
__device__ __forceinline__ float f2lo(unsigned long long v) { return __uint_as_float((unsigned)v); }
__device__ __forceinline__ float f2hi(unsigned long long v) { return __uint_as_float((unsigned)(v >> 32)); }

// ---------------- init ----------------
__global__ void initKernel() {
    int t = threadIdx.x;
    if (t < BB*MM) g_v[t] = 0.f;
    if (t == 0) { g_done = 0; g_bar_count = 0u; g_bar_gen = 0u; }
}

// ---------------- nu from score_map ----------------
__global__ void nuKernel(const float* __restrict__ score) {
    __shared__ int cnt[MM];
    int b = blockIdx.x, tid = threadIdx.x;
    if (tid < MM) cnt[tid] = 0;
    __syncthreads();
    const float* sb = score + (long)b * MM * NN;
    for (int p = tid; p < NN; p += 256) {
        float best = sb[p]; int bi = 0;
        #pragma unroll
        for (int k = 1; k < MM; ++k) {
            float v = sb[k*NN + p];
            if (v > best) { best = v; bi = k; }
        }
        atomicAdd(&cnt[bi], 1);
    }
    __syncthreads();
    if (tid < MM) {
        float t0 = (float)cnt[tid] / ((float)NN + 1e-8f) + 1e-6f;
        float s = t0;
        #pragma unroll
        for (int o = 16; o; o >>= 1) s += __shfl_xor_sync(0xffffffffu, s, o);
        g_nu[b*MM + tid] = t0 / s;
    }
}

// ---------------- cost + K : register-tiled, no shuffles ----------------
// 512 blocks = 16 b x 32 row-blocks(128 rows). 256 thr: tx=m(32), ty=rowgrp(8)x16rows
__global__ void __launch_bounds__(256) costKernel(const float* __restrict__ x,
                                                  const float* __restrict__ y) {
    __shared__ float xs[128*33];     // padded rows of 33
    __shared__ float ys[32*33];
    __shared__ float xinvs[128];
    __shared__ float yinvs[32];
    int tid = threadIdx.x, tx = tid & 31, ty = tid >> 5;
    int b = blockIdx.x >> 5, rb = blockIdx.x & 31;
    int row0 = rb * 128;

    float acc[16];
    #pragma unroll
    for (int i = 0; i < 16; ++i) acc[i] = 0.f;
    float xn = 0.f, yn = 0.f;

    for (int kc = 0; kc < CC; kc += 32) {
        __syncthreads();
        // x chunk: 128 rows x 32 k
        #pragma unroll
        for (int pass = 0; pass < 4; ++pass) {
            int r = pass*32 + (tid >> 3);
            int kk = (tid & 7) * 4;
            float4 v = *(const float4*)(x + ((long)b*NN + row0 + r)*CC + kc + kk);
            xs[r*33 + kk]   = v.x; xs[r*33 + kk+1] = v.y;
            xs[r*33 + kk+2] = v.z; xs[r*33 + kk+3] = v.w;
        }
        // y chunk: 32 m x 32 k
        {
            int m = tid >> 3, kk = (tid & 7) * 4;
            float4 v = *(const float4*)(y + ((long)b*MM + m)*CC + kc + kk);
            ys[m*33 + kk]   = v.x; ys[m*33 + kk+1] = v.y;
            ys[m*33 + kk+2] = v.z; ys[m*33 + kk+3] = v.w;
        }
        __syncthreads();
        if (tid < 128) {
            #pragma unroll
            for (int k = 0; k < 32; ++k) { float v = xs[tid*33 + k]; xn += v*v; }
        }
        if (tid < 32) {
            #pragma unroll
            for (int k = 0; k < 32; ++k) { float v = ys[tid*33 + k]; yn += v*v; }
        }
        #pragma unroll 4
        for (int k = 0; k < 32; ++k) {
            float bv = ys[tx*33 + k];
            #pragma unroll
            for (int i = 0; i < 16; ++i)
                acc[i] += xs[(ty*16 + i)*33 + k] * bv;
        }
    }
    if (tid < 128) xinvs[tid] = rsqrtf(xn);
    if (tid < 32)  yinvs[tid] = rsqrtf(yn);
    __syncthreads();
    float yi = yinvs[tx];
    #pragma unroll
    for (int i = 0; i < 16; ++i) {
        int r = ty*16 + i;
        float c = 1.f - acc[i] * xinvs[r] * yi;
        long idx = ((long)b*NN + row0 + r) * MM + tx;
        g_cost[idx] = c;
        g_Kmat[idx] = expf(-c * 20.0f);
    }
}

// ---------------- sinkhorn: persistent, K cached in smem, 256 blocks ----------------
__device__ __forceinline__ void gbar() {
    __threadfence();
    __syncthreads();
    if (threadIdx.x == 0) {
        unsigned my = *(volatile unsigned*)&g_bar_gen;
        if (atomicAdd(&g_bar_count, 1u) == (SINK_BLOCKS - 1u)) {
            atomicExch(&g_bar_count, 0u);
            __threadfence();
            atomicAdd(&g_bar_gen, 1u);
        } else {
            while (*(volatile unsigned*)&g_bar_gen == my) { __nanosleep(64); }
        }
        __threadfence();
    }
    __syncthreads();
}

__global__ void __launch_bounds__(256) sinkhornKernel() {
    __shared__ float ks[8 * 32 * 33];      // 33.8 KB
    int tid = threadIdx.x, lane = tid & 31, wid = tid >> 5;
    int gw = blockIdx.x * 8 + wid;          // 0..2047
    int b = gw >> 7, chunk = gw & 127;      // 128 chunks of 32 rows per batch
    long rowbase = (long)b*NN + chunk*32;
    float* kw = ks + wid * (32*33);

    // cache this warp's K tile: 32 rows x 32 m, pad 33
    for (int r = 0; r < 32; ++r)
        kw[r*33 + lane] = g_Kmat[(rowbase + r)*MM + lane];
    __syncwarp();

    float uprev = 0.f;
    for (int it = 0; it < 50; ++it) {
        if (*(volatile int*)&g_done) break;

        float vreg = __ldcg(&g_v[b*MM + lane]);
        // s_row (row = lane) = sum_m K[row][m] * v[m]
        float s = 0.f;
        #pragma unroll
        for (int m = 0; m < 32; ++m)
            s += kw[lane*33 + m] * __shfl_sync(0xffffffffu, vreg, m);
        float un = MUVAL / (s + 1e-8f);
        float errl = fabsf(un - uprev);
        uprev = un;
        // (K^T u)[m] partial for m = lane over this warp's 32 rows
        float acc = 0.f;
        #pragma unroll
        for (int j = 0; j < 32; ++j)
            acc += kw[j*33 + lane] * __shfl_sync(0xffffffffu, un, j);
        __stcg(&g_spart[gw*MM + lane], acc);
        #pragma unroll
        for (int o = 16; o; o >>= 1) errl += __shfl_xor_sync(0xffffffffu, errl, o);
        if (lane == 0) __stcg(&g_errpart[gw], errl);
        gbar();

        if (gw < 512) {   // v update: warp per (b, m-half)... (bb = gw>>5, m = gw&31)
            int bb = gw >> 5, m = gw & 31;
            float ss = 0.f;
            #pragma unroll
            for (int j = 0; j < 4; ++j)
                ss += __ldcg(&g_spart[((long)bb*128 + lane + 32*j)*MM + m]);
            #pragma unroll
            for (int o = 16; o; o >>= 1) ss += __shfl_xor_sync(0xffffffffu, ss, o);
            if (lane == 0) __stcg(&g_v[bb*MM + m], g_nu[bb*MM + m] / (ss + 1e-8f));
        }
        if (gw == 2047) { // global err check
            float e = 0.f;
            for (int j = lane; j < 2048; j += 32) e += __ldcg(&g_errpart[j]);
            #pragma unroll
            for (int o = 16; o; o >>= 1) e += __shfl_xor_sync(0xffffffffu, e, o);
            if (lane == 0 && (e / (float)BB) < 0.1f) {
                *(volatile int*)&g_done = 1;
                __threadfence();
            }
        }
        gbar();
    }
    g_u[rowbase + lane] = uprev;
}

// ---------------- Y2 = y @ W2 : 64 blocks ----------------
__global__ void __launch_bounds__(256) y2Kernel(const float* __restrict__ y,
                                                const float* __restrict__ W) {
    __shared__ float ys[MM][64];
    int tid = threadIdx.x;
    int b = blockIdx.x >> 2, c0 = (blockIdx.x & 3) * 128;
    int col = c0 + (tid & 127), mh = tid >> 7;
    const float* W2 = W + 512*512;
    float acc[16];
    #pragma unroll
    for (int i = 0; i < 16; ++i) acc[i] = 0.f;

    for (int kc = 0; kc < CC; kc += 64) {
        __syncthreads();
        {
            int m = tid >> 3, k4 = (tid & 7) * 8;
            float4 v0 = *(const float4*)(y + ((long)b*MM + m)*CC + kc + k4);
            float4 v1 = *(const float4*)(y + ((long)b*MM + m)*CC + kc + k4 + 4);
            *(float4*)&ys[m][k4]     = v0;
            *(float4*)&ys[m][k4 + 4] = v1;
        }
        __syncthreads();
        #pragma unroll 4
        for (int k = 0; k < 64; ++k) {
            float w = W2[(long)(kc + k)*CC + col];
            #pragma unroll
            for (int i = 0; i < 16; ++i) acc[i] += ys[mh*16 + i][k] * w;
        }
    }
    #pragma unroll
    for (int i = 0; i < 16; ++i)
        g_y2[((long)b*MM + mh*16 + i)*CC + col] = acc[i];
}

// ---------------- pi, pi_norm, ot partials ----------------
__global__ void __launch_bounds__(256) piKernel(float* __restrict__ d_pi, int write_pi) {
    int tid = threadIdx.x, lane = tid & 31, wid = tid >> 5;
    int gw = blockIdx.x * 8 + wid;           // 0..2047
    int b = gw >> 7, sub = gw & 127;
    float vv = g_v[b*MM + lane];
    float ot = 0.f;
    for (int r = 0; r < 32; ++r) {
        int n = sub*32 + r;
        long idx = ((long)b*NN + n) * MM + lane;
        float pi = g_u[b*NN + n] * g_Kmat[idx] * vv;
        float rs = pi;
        #pragma unroll
        for (int o = 16; o; o >>= 1) rs += __shfl_xor_sync(0xffffffffu, rs, o);
        g_pinorm[idx] = pi / (rs + 1e-8f);
        if (write_pi) d_pi[idx] = pi;
        ot += pi * g_cost[idx];
    }
    #pragma unroll
    for (int o = 16; o; o >>= 1) ot += __shfl_xor_sync(0xffffffffu, ot, o);
    if (lane == 0) g_otpart[gw] = ot;
}

__global__ void otReduceKernel(float* __restrict__ d_ot) {
    int lane = threadIdx.x & 31, b = threadIdx.x >> 5;
    float s = g_otpart[b*128 + lane] + g_otpart[b*128 + lane + 32]
            + g_otpart[b*128 + lane + 64] + g_otpart[b*128 + lane + 96];
    #pragma unroll
    for (int o = 16; o; o >>= 1) s += __shfl_xor_sync(0xffffffffu, s, o);
    if (lane == 0) d_ot[b] = s;
}

// ---------------- main GEMM: out = x@W1 + pinorm@Y2[b] + bias (pre-LN) ----------------
// 2048 blocks = 512 rowTiles x 4 colTiles. 256 thr, 8x8 micro via fma.rn.f32x2,
// double-buffered K=16 chunks (32 for X/W1 + 2 for P/Y2).
__global__ void __launch_bounds__(256, 2) gemmKernel(const float* __restrict__ x,
                                                     const float* __restrict__ W,
                                                     const float* __restrict__ bias,
                                                     float* __restrict__ out) {
    __shared__ float As[2][16*128];
    __shared__ float Bs[2][16*128];
    int tid = threadIdx.x;
    int tx = tid & 15, ty = tid >> 4;
    int rowTile = blockIdx.x >> 2, colTile = blockIdx.x & 3;
    int row0 = rowTile * 128, c0 = colTile * 128;
    int b = row0 >> 12;
    int ar = tid >> 1, ak = (tid & 1) * 8;
    int bk = tid >> 4, bc = (tid & 15) * 4;

    unsigned long long acc[8][4];
    #pragma unroll
    for (int i = 0; i < 8; ++i)
        #pragma unroll
        for (int j = 0; j < 4; ++j) acc[i][j] = 0ull;

    const float* xrow = x + (long)(row0 + ar) * CC;
    const float* prow = g_pinorm + (long)(row0 + ar) * MM;
    const float* y2b  = g_y2 + (long)b * MM * CC;

    float4 av0, av1, bv0, bv1;
    // prologue: chunk 0
    av0 = *(const float4*)(xrow + ak);
    av1 = *(const float4*)(xrow + ak + 4);
    bv0 = *(const float4*)(W + (long)bk*CC + c0 + bc);
    bv1 = *(const float4*)(W + (long)bk*CC + c0 + bc + 64);
    {
        float* Ad = As[0]; float* Bd = Bs[0];
        Ad[(ak+0)*128+ar]=av0.x; Ad[(ak+1)*128+ar]=av0.y; Ad[(ak+2)*128+ar]=av0.z; Ad[(ak+3)*128+ar]=av0.w;
        Ad[(ak+4)*128+ar]=av1.x; Ad[(ak+5)*128+ar]=av1.y; Ad[(ak+6)*128+ar]=av1.z; Ad[(ak+7)*128+ar]=av1.w;
        *(float4*)(Bd + bk*128 + bc)      = bv0;
        *(float4*)(Bd + bk*128 + bc + 64) = bv1;
    }
    __syncthreads();

    for (int cc = 0; cc < 34; ++cc) {
        int buf = cc & 1;
        if (cc < 33) {
            int nc = cc + 1;
            if (nc < 32) {
                av0 = *(const float4*)(xrow + nc*16 + ak);
                av1 = *(const float4*)(xrow + nc*16 + ak + 4);
                bv0 = *(const float4*)(W + (long)(nc*16 + bk)*CC + c0 + bc);
                bv1 = *(const float4*)(W + (long)(nc*16 + bk)*CC + c0 + bc + 64);
            } else {
                int t = (nc - 32) * 16;
                av0 = *(const float4*)(prow + t + ak);
                av1 = *(const float4*)(prow + t + ak + 4);
                bv0 = *(const float4*)(y2b + (long)(t + bk)*CC + c0 + bc);
                bv1 = *(const float4*)(y2b + (long)(t + bk)*CC + c0 + bc + 64);
            }
        }
        const float* Ab = As[buf];
        const float* Bb = Bs[buf];
        #pragma unroll
        for (int kk = 0; kk < 16; ++kk) {
            float4 a0 = *(const float4*)(Ab + kk*128 + ty*8);
            float4 a1 = *(const float4*)(Ab + kk*128 + ty*8 + 4);
            unsigned long long a2[8];
            a2[0]=pack2(a0.x); a2[1]=pack2(a0.y); a2[2]=pack2(a0.z); a2[3]=pack2(a0.w);
            a2[4]=pack2(a1.x); a2[5]=pack2(a1.y); a2[6]=pack2(a1.z); a2[7]=pack2(a1.w);
            const unsigned long long* bp  = (const unsigned long long*)(Bb + kk*128 + tx*4);
            const unsigned long long* bp2 = (const unsigned long long*)(Bb + kk*128 + tx*4 + 64);
            unsigned long long b2[4];
            b2[0]=bp[0]; b2[1]=bp[1]; b2[2]=bp2[0]; b2[3]=bp2[1];
            #pragma unroll
            for (int i = 0; i < 8; ++i)
                #pragma unroll
                for (int j = 0; j < 4; ++j)
                    fma2(acc[i][j], a2[i], b2[j]);
        }
        if (cc < 33) {
            __syncthreads();
            float* Ad = As[buf ^ 1]; float* Bd = Bs[buf ^ 1];
            Ad[(ak+0)*128+ar]=av0.x; Ad[(ak+1)*128+ar]=av0.y; Ad[(ak+2)*128+ar]=av0.z; Ad[(ak+3)*128+ar]=av0.w;
            Ad[(ak+4)*128+ar]=av1.x; Ad[(ak+5)*128+ar]=av1.y; Ad[(ak+6)*128+ar]=av1.z; Ad[(ak+7)*128+ar]=av1.w;
            *(float4*)(Bd + bk*128 + bc)      = bv0;
            *(float4*)(Bd + bk*128 + bc + 64) = bv1;
            __syncthreads();
        }
    }

    // epilogue: + bias, write pre-LN
    #pragma unroll
    for (int i = 0; i < 8; ++i) {
        long orow = row0 + ty*8 + i;
        int cA = c0 + tx*4, cB = cA + 64;
        float4 o;
        o.x = f2lo(acc[i][0]) + bias[cA+0];
        o.y = f2hi(acc[i][0]) + bias[cA+1];
        o.z = f2lo(acc[i][1]) + bias[cA+2];
        o.w = f2hi(acc[i][1]) + bias[cA+3];
        *(float4*)(out + orow*CC + cA) = o;
        o.x = f2lo(acc[i][2]) + bias[cB+0];
        o.y = f2hi(acc[i][2]) + bias[cB+1];
        o.z = f2lo(acc[i][3]) + bias[cB+2];
        o.w = f2hi(acc[i][3]) + bias[cB+3];
        *(float4*)(out + orow*CC + cB) = o;
    }
}

// ---------------- LayerNorm in-place, warp per row ----------------
__global__ void __launch_bounds__(256) lnKernel(float* __restrict__ out,
                                                const float* __restrict__ gamma,
                                                const float* __restrict__ beta) {
    int tid = threadIdx.x, lane = tid & 31, wid = tid >> 5;
    long row = (long)blockIdx.x * 8 + wid;
    float4* rp = (float4*)(out + row * CC);
    float4 v[4];
    float sum = 0.f;
    #pragma unroll
    for (int j = 0; j < 4; ++j) {
        v[j] = rp[lane + j*32];
        sum += v[j].x + v[j].y + v[j].z + v[j].w;
    }
    #pragma unroll
    for (int o = 16; o; o >>= 1) sum += __shfl_xor_sync(0xffffffffu, sum, o);
    float mean = sum * (1.0f/512.0f);
    float var = 0.f;
    #pragma unroll
    for (int j = 0; j < 4; ++j) {
        float dx = v[j].x - mean, dy = v[j].y - mean, dz = v[j].z - mean, dw = v[j].w - mean;
        var += dx*dx + dy*dy + dz*dz + dw*dw;
    }
    #pragma unroll
    for (int o = 16; o; o >>= 1) var += __shfl_xor_sync(0xffffffffu, var, o);
    float rs = rsqrtf(var * (1.0f/512.0f) + 1e-5f);
    const float4* g4 = (const float4*)gamma;
    const float4* b4 = (const float4*)beta;
    #pragma unroll
    for (int j = 0; j < 4; ++j) {
        float4 g = g4[lane + j*32], bt = b4[lane + j*32];
        float4 o;
        o.x = (v[j].x - mean)*rs*g.x + bt.x;
        o.y = (v[j].y - mean)*rs*g.y + bt.y;
        o.z = (v[j].z - mean)*rs*g.z + bt.z;
        o.w = (v[j].w - mean)*rs*g.w + bt.w;
        rp[lane + j*32] = o;
    }
}

// ---------------- launch ----------------
extern "C" void kernel_launch(void* const* d_in, const int* in_sizes, int n_in,
                              void* d_out, int out_size) {
    const float* x     = (const float*)d_in[0];
    const float* y     = (const float*)d_in[1];
    const float* score = (const float*)d_in[2];
    const float* W     = (const float*)d_in[3];
    const float* bias  = (const float*)d_in[4];
    const float* gamma = (const float*)d_in[5];
    const float* beta  = (const float*)d_in[6];
    float* out = (float*)d_out;

    const long OUT_ELEMS = (long)BB*NN*CC;
    int full = (out_size >= (int)(OUT_ELEMS + BB + (long)BB*NN*MM));
    float* d_ot = full ? out + OUT_ELEMS : nullptr;
    float* d_pi = full ? out + OUT_ELEMS + BB : nullptr;

    initKernel<<<1, 512>>>();
    nuKernel<<<BB, 256>>>(score);
    costKernel<<<512, 256>>>(x, y);
    sinkhornKernel<<<SINK_BLOCKS, 256>>>();
    y2Kernel<<<64, 256>>>(y, W);
    piKernel<<<256, 256>>>(d_pi, full);
    if (full) otReduceKernel<<<1, 512>>>(d_ot);
    gemmKernel<<<2048, 256>>>(x, W, bias, out);
    lnKernel<<<8192, 256>>>(out, gamma, beta);
}

// round 10
// speedup vs baseline: 6.7157x; 1.6867x over previous
#include <cuda_runtime.h>
#include <cuda_bf16.h>
#include <math.h>
#include <stdint.h>

#define BB 16
#define NN 4096
#define MM 32
#define CC 512
#define MUVAL (1.0f/4096.0f)

__device__ float g_cost[BB*NN*MM];
__device__ float g_Kmat[BB*NN*MM];
__device__ float g_u[BB*NN];
__device__ float g_v[BB*MM];
__device__ float g_nu[BB*MM];
__device__ float g_sblk[2][256*MM];
__device__ float g_errblk[2][256];
__device__ float g_otpart[2048];
__device__ __nv_bfloat16 g_xhi[BB*NN*CC];
__device__ __nv_bfloat16 g_xlo[BB*NN*CC];
__device__ __nv_bfloat16 g_phi[BB*NN*MM];
__device__ __nv_bfloat16 g_plo[BB*NN*MM];
__device__ __nv_bfloat16 g_wthi[CC*CC];   // [n][k]
__device__ __nv_bfloat16 g_wtlo[CC*CC];
__device__ __nv_bfloat16 g_y2thi[BB*CC*MM]; // [b][n][m]
__device__ __nv_bfloat16 g_y2tlo[BB*CC*MM];
__device__ unsigned g_bar1[16];
__device__ unsigned g_bar2;
__device__ unsigned g_bar_gen;

__device__ __forceinline__ uint32_t smem_u32(const void* p) {
    uint32_t a;
    asm("{ .reg .u64 t; cvta.to.shared.u64 t, %1; cvt.u32.u64 %0, t; }" : "=r"(a) : "l"(p));
    return a;
}
__device__ __forceinline__ void ldsm4(uint32_t* f, uint32_t addr) {
    asm volatile("ldmatrix.sync.aligned.m8n8.x4.shared.b16 {%0,%1,%2,%3}, [%4];"
        : "=r"(f[0]), "=r"(f[1]), "=r"(f[2]), "=r"(f[3]) : "r"(addr));
}
__device__ __forceinline__ void mma16816(float* c, const uint32_t* a, const uint32_t* b) {
    asm volatile("mma.sync.aligned.m16n8k16.row.col.f32.bf16.bf16.f32 "
        "{%0,%1,%2,%3}, {%4,%5,%6,%7}, {%8,%9}, {%0,%1,%2,%3};"
        : "+f"(c[0]), "+f"(c[1]), "+f"(c[2]), "+f"(c[3])
        : "r"(a[0]), "r"(a[1]), "r"(a[2]), "r"(a[3]), "r"(b[0]), "r"(b[1]));
}
__device__ __forceinline__ void cpa16(uint32_t dst, const void* src) {
    asm volatile("cp.async.cg.shared.global [%0], [%1], 16;" :: "r"(dst), "l"(src));
}
#define CP_COMMIT() asm volatile("cp.async.commit_group;" ::: "memory")
#define CP_WAIT(n)  asm volatile("cp.async.wait_group %0;" :: "n"(n) : "memory")

__device__ __forceinline__ void split_bf16(float v, __nv_bfloat16& h, __nv_bfloat16& l) {
    h = __float2bfloat16(v);
    l = __float2bfloat16(v - __bfloat162float(h));
}

__global__ void initKernel() {
    int t = threadIdx.x;
    if (t < 16) g_bar1[t] = 0u;
    if (t == 0) { g_bar2 = 0u; g_bar_gen = 0u; }
}

__global__ void nuKernel(const float* __restrict__ score) {
    __shared__ int cnt[MM];
    int b = blockIdx.x, tid = threadIdx.x;
    if (tid < MM) cnt[tid] = 0;
    __syncthreads();
    const float* sb = score + (long)b * MM * NN;
    for (int p = tid; p < NN; p += 256) {
        float best = sb[p]; int bi = 0;
        #pragma unroll
        for (int k = 1; k < MM; ++k) {
            float v = sb[k*NN + p];
            if (v > best) { best = v; bi = k; }
        }
        atomicAdd(&cnt[bi], 1);
    }
    __syncthreads();
    if (tid < MM) {
        float t0 = (float)cnt[tid] / ((float)NN + 1e-8f) + 1e-6f;
        float s = t0;
        #pragma unroll
        for (int o = 16; o; o >>= 1) s += __shfl_xor_sync(0xffffffffu, s, o);
        g_nu[b*MM + tid] = t0 / s;
    }
}

// W1^T -> bf16 hi/lo [n][k]
__global__ void __launch_bounds__(256) wtKernel(const float* __restrict__ W) {
    __shared__ float t[32][33];
    int bx = blockIdx.x & 15, by = blockIdx.x >> 4;
    int tx = threadIdx.x & 31, ty = threadIdx.x >> 5;
    int k0 = by*32, n0 = bx*32;
    #pragma unroll
    for (int j = 0; j < 4; ++j)
        t[ty + 8*j][tx] = W[(long)(k0 + ty + 8*j)*CC + n0 + tx];
    __syncthreads();
    #pragma unroll
    for (int j = 0; j < 4; ++j) {
        int n = n0 + ty + 8*j, k = k0 + tx;
        __nv_bfloat16 h, l; split_bf16(t[tx][ty + 8*j], h, l);
        g_wthi[(long)n*CC + k] = h;
        g_wtlo[(long)n*CC + k] = l;
    }
}

// cost + K + X hi/lo
__global__ void __launch_bounds__(256) costKernel(const float* __restrict__ x,
                                                  const float* __restrict__ y) {
    __shared__ float xs[128*33];
    __shared__ float ys[32*33];
    __shared__ float xinvs[128];
    __shared__ float yinvs[32];
    int tid = threadIdx.x, tx = tid & 31, ty = tid >> 5;
    int b = blockIdx.x >> 5, rb = blockIdx.x & 31;
    int row0 = rb * 128;
    float acc[16];
    #pragma unroll
    for (int i = 0; i < 16; ++i) acc[i] = 0.f;
    float xn = 0.f, yn = 0.f;
    for (int kc = 0; kc < CC; kc += 32) {
        __syncthreads();
        #pragma unroll
        for (int pass = 0; pass < 4; ++pass) {
            int r = pass*32 + (tid >> 3), kk = (tid & 7) * 4;
            long gidx = ((long)b*NN + row0 + r)*CC + kc + kk;
            float4 v = *(const float4*)(x + gidx);
            xs[r*33 + kk] = v.x; xs[r*33 + kk+1] = v.y; xs[r*33 + kk+2] = v.z; xs[r*33 + kk+3] = v.w;
            __nv_bfloat16 h0,l0,h1,l1,h2,l2,h3,l3;
            split_bf16(v.x,h0,l0); split_bf16(v.y,h1,l1); split_bf16(v.z,h2,l2); split_bf16(v.w,h3,l3);
            __nv_bfloat162* ph = (__nv_bfloat162*)(g_xhi + gidx);
            __nv_bfloat162* pl = (__nv_bfloat162*)(g_xlo + gidx);
            ph[0] = __halves2bfloat162(h0,h1); ph[1] = __halves2bfloat162(h2,h3);
            pl[0] = __halves2bfloat162(l0,l1); pl[1] = __halves2bfloat162(l2,l3);
        }
        {
            int m = tid >> 3, kk = (tid & 7) * 4;
            float4 v = *(const float4*)(y + ((long)b*MM + m)*CC + kc + kk);
            ys[m*33 + kk] = v.x; ys[m*33 + kk+1] = v.y; ys[m*33 + kk+2] = v.z; ys[m*33 + kk+3] = v.w;
        }
        __syncthreads();
        if (tid < 128) {
            #pragma unroll
            for (int k = 0; k < 32; ++k) { float v = xs[tid*33 + k]; xn += v*v; }
        }
        if (tid < 32) {
            #pragma unroll
            for (int k = 0; k < 32; ++k) { float v = ys[tid*33 + k]; yn += v*v; }
        }
        #pragma unroll 4
        for (int k = 0; k < 32; ++k) {
            float bv = ys[tx*33 + k];
            #pragma unroll
            for (int i = 0; i < 16; ++i)
                acc[i] += xs[(ty*16 + i)*33 + k] * bv;
        }
    }
    if (tid < 128) xinvs[tid] = rsqrtf(xn);
    if (tid < 32)  yinvs[tid] = rsqrtf(yn);
    __syncthreads();
    float yi = yinvs[tx];
    #pragma unroll
    for (int i = 0; i < 16; ++i) {
        int r = ty*16 + i;
        float c = 1.f - acc[i] * xinvs[r] * yi;
        long idx = ((long)b*NN + row0 + r) * MM + tx;
        g_cost[idx] = c;
        g_Kmat[idx] = expf(-c * 20.0f);
    }
}

// sinkhorn: 256 persistent blocks, one tree barrier per iteration
__device__ __forceinline__ void gbar() {
    __threadfence();
    __syncthreads();
    if (threadIdx.x == 0) {
        unsigned my = *(volatile unsigned*)&g_bar_gen;
        unsigned a = atomicAdd(&g_bar1[blockIdx.x >> 4], 1u) + 1u;
        if ((a & 15u) == 0u) {
            unsigned b2 = atomicAdd(&g_bar2, 1u) + 1u;
            if ((b2 & 15u) == 0u) atomicAdd(&g_bar_gen, 1u);
        }
        while (*(volatile unsigned*)&g_bar_gen == my) __nanosleep(32);
        __threadfence();
    }
    __syncthreads();
}

__global__ void __launch_bounds__(256) sinkhornKernel() {
    __shared__ float ks[8*32*33];
    __shared__ float wacc[8][32];
    __shared__ float werr[8];
    int tid = threadIdx.x, lane = tid & 31, wid = tid >> 5;
    int blk = blockIdx.x, gw = blk*8 + wid;
    int b = gw >> 7, chunk = gw & 127;
    long rowbase = (long)b*NN + chunk*32;
    float* kw = ks + wid*(32*33);
    for (int r = 0; r < 32; ++r)
        kw[r*33 + lane] = g_Kmat[(rowbase + r)*MM + lane];
    __syncwarp();
    float uprev = 0.f, vreg = 0.f;
    for (int it = 0; it < 50; ++it) {
        int buf = it & 1;
        float s = 0.f;
        #pragma unroll
        for (int m = 0; m < 32; ++m)
            s += kw[lane*33 + m] * __shfl_sync(0xffffffffu, vreg, m);
        float un = MUVAL / (s + 1e-8f);
        float errl = fabsf(un - uprev);
        uprev = un;
        float acc = 0.f;
        #pragma unroll
        for (int j = 0; j < 32; ++j)
            acc += kw[j*33 + lane] * __shfl_sync(0xffffffffu, un, j);
        #pragma unroll
        for (int o = 16; o; o >>= 1) errl += __shfl_xor_sync(0xffffffffu, errl, o);
        wacc[wid][lane] = acc;
        if (lane == 0) werr[wid] = errl;
        __syncthreads();
        if (wid == 0) {
            float ba = wacc[0][lane]+wacc[1][lane]+wacc[2][lane]+wacc[3][lane]
                     + wacc[4][lane]+wacc[5][lane]+wacc[6][lane]+wacc[7][lane];
            __stcg(&g_sblk[buf][blk*32 + lane], ba);
            if (lane == 0)
                __stcg(&g_errblk[buf][blk],
                       werr[0]+werr[1]+werr[2]+werr[3]+werr[4]+werr[5]+werr[6]+werr[7]);
        }
        gbar();
        float ss = 0.f;
        #pragma unroll
        for (int j = 0; j < 16; ++j)
            ss += __ldcg(&g_sblk[buf][(b*16 + j)*32 + lane]);
        vreg = g_nu[b*MM + lane] / (ss + 1e-8f);
        float e = 0.f;
        #pragma unroll
        for (int j = 0; j < 8; ++j)
            e += __ldcg(&g_errblk[buf][lane + 32*j]);
        #pragma unroll
        for (int o = 16; o; o >>= 1) e += __shfl_xor_sync(0xffffffffu, e, o);
        if (e * (1.0f/16.0f) < 0.1f) break;
    }
    g_u[rowbase + lane] = uprev;
    if (chunk == 0) g_v[b*MM + lane] = vreg;
}

// Y2^T -> bf16 hi/lo [b][n][m]
__global__ void __launch_bounds__(256) y2Kernel(const float* __restrict__ y,
                                                const float* __restrict__ W) {
    __shared__ float ys[MM][64];
    int tid = threadIdx.x;
    int b = blockIdx.x >> 2, c0 = (blockIdx.x & 3) * 128;
    int col = c0 + (tid & 127), mh = tid >> 7;
    const float* W2 = W + 512*512;
    float acc[16];
    #pragma unroll
    for (int i = 0; i < 16; ++i) acc[i] = 0.f;
    for (int kc = 0; kc < CC; kc += 64) {
        __syncthreads();
        {
            int m = tid >> 3, k4 = (tid & 7) * 8;
            *(float4*)&ys[m][k4]     = *(const float4*)(y + ((long)b*MM + m)*CC + kc + k4);
            *(float4*)&ys[m][k4 + 4] = *(const float4*)(y + ((long)b*MM + m)*CC + kc + k4 + 4);
        }
        __syncthreads();
        #pragma unroll 4
        for (int k = 0; k < 64; ++k) {
            float w = W2[(long)(kc + k)*CC + col];
            #pragma unroll
            for (int i = 0; i < 16; ++i) acc[i] += ys[mh*16 + i][k] * w;
        }
    }
    #pragma unroll
    for (int i = 0; i < 16; ++i) {
        __nv_bfloat16 h, l; split_bf16(acc[i], h, l);
        long idx = ((long)b*CC + col)*MM + mh*16 + i;
        g_y2thi[idx] = h;
        g_y2tlo[idx] = l;
    }
}

__global__ void __launch_bounds__(256) piKernel(float* __restrict__ d_pi, int write_pi) {
    int tid = threadIdx.x, lane = tid & 31, wid = tid >> 5;
    int gw = blockIdx.x * 8 + wid;
    int b = gw >> 7, sub = gw & 127;
    float vv = g_v[b*MM + lane];
    float ot = 0.f;
    for (int r = 0; r < 32; ++r) {
        int n = sub*32 + r;
        long idx = ((long)b*NN + n) * MM + lane;
        float pi = g_u[b*NN + n] * g_Kmat[idx] * vv;
        float rs = pi;
        #pragma unroll
        for (int o = 16; o; o >>= 1) rs += __shfl_xor_sync(0xffffffffu, rs, o);
        float pn = pi / (rs + 1e-8f);
        __nv_bfloat16 h, l; split_bf16(pn, h, l);
        g_phi[idx] = h; g_plo[idx] = l;
        if (write_pi) d_pi[idx] = pi;
        ot += pi * g_cost[idx];
    }
    #pragma unroll
    for (int o = 16; o; o >>= 1) ot += __shfl_xor_sync(0xffffffffu, ot, o);
    if (lane == 0) g_otpart[gw] = ot;
}

__global__ void otReduceKernel(float* __restrict__ d_ot) {
    int lane = threadIdx.x & 31, b = threadIdx.x >> 5;
    float s = g_otpart[b*128 + lane] + g_otpart[b*128 + lane + 32]
            + g_otpart[b*128 + lane + 64] + g_otpart[b*128 + lane + 96];
    #pragma unroll
    for (int o = 16; o; o >>= 1) s += __shfl_xor_sync(0xffffffffu, s, o);
    if (lane == 0) d_ot[b] = s;
}

// ---- HMMA GEMM: out = X@W1 + P@Y2 + bias. 2048 CTAs (512 rowTiles x 4 colTiles) ----
// smem stage: Ahi[128x72bf16] Alo Bhi[128x72] Blo, pitch 144B. double buffered.
#define PITCH 144
#define A_LO 18432
#define B_HI 36864
#define B_LO 55296
#define STAGE 73728
#define GSMEM (2*STAGE)

__device__ __forceinline__ void ldA(uint32_t base, int wr0, int mi, int ks, int lane, uint32_t* f) {
    uint32_t addr = base + (uint32_t)(wr0 + mi*16 + (lane & 15))*PITCH
                  + (uint32_t)(ks*16 + ((lane >> 4) << 3))*2;
    ldsm4(f, addr);
}
__device__ __forceinline__ void ldB(uint32_t base, int wn0, int pair, int ks, int lane, uint32_t* f) {
    int row = wn0 + pair*16 + (lane & 7) + ((lane >> 4) & 1)*8;
    int col = ks*16 + (lane & 8);
    ldsm4(f, base + (uint32_t)row*PITCH + (uint32_t)col*2);
}

__device__ __forceinline__ void computeChunk(uint32_t sbase, int wr0, int wn0, int lane,
                                             float acc[4][4][4], int nks) {
    for (int ks = 0; ks < nks; ++ks) {
        uint32_t ah[4][4], al[4][4];
        #pragma unroll
        for (int mi = 0; mi < 4; ++mi) {
            ldA(sbase, wr0, mi, ks, lane, ah[mi]);
            ldA(sbase + A_LO, wr0, mi, ks, lane, al[mi]);
        }
        uint32_t bh[2][4], bl[2][4];
        #pragma unroll
        for (int p = 0; p < 2; ++p) {
            ldB(sbase + B_HI, wn0, p, ks, lane, bh[p]);
            ldB(sbase + B_LO, wn0, p, ks, lane, bl[p]);
        }
        #pragma unroll
        for (int mi = 0; mi < 4; ++mi)
            #pragma unroll
            for (int ni = 0; ni < 4; ++ni) {
                const uint32_t* bhp = &bh[ni >> 1][(ni & 1)*2];
                const uint32_t* blp = &bl[ni >> 1][(ni & 1)*2];
                mma16816(acc[mi][ni], ah[mi], bhp);
                mma16816(acc[mi][ni], ah[mi], blp);
                mma16816(acc[mi][ni], al[mi], bhp);
            }
    }
}

__global__ void __launch_bounds__(256) gemmMMA(const float* __restrict__ bias,
                                               float* __restrict__ out) {
    extern __shared__ char sm[];
    uint32_t sb = smem_u32(sm);
    int tid = threadIdx.x, lane = tid & 31, wid = tid >> 5;
    int rowTile = blockIdx.x >> 2, colTile = blockIdx.x & 3;
    int row0 = rowTile*128, n0 = colTile*128;
    int b = rowTile >> 5;
    int wr0 = (wid >> 2)*64, wn0 = (wid & 3)*32;

    float acc[4][4][4];
    #pragma unroll
    for (int i = 0; i < 4; ++i)
        #pragma unroll
        for (int j = 0; j < 4; ++j)
            #pragma unroll
            for (int q = 0; q < 4; ++q) acc[i][j][q] = 0.f;

    // per-thread slots: u = tid + i*256 -> r = u>>3 (0..127), k16 = u&7
    int r_ = tid >> 3, k16_ = tid & 7;

    // prologue chunk 0
    #pragma unroll
    for (int i = 0; i < 4; ++i) {
        int r = r_ + i*32;
        uint32_t so = (uint32_t)r*PITCH + (uint32_t)k16_*16;
        long ga = ((long)(row0 + r)*CC)*2 + k16_*16;
        long gb = ((long)(n0   + r)*CC)*2 + k16_*16;
        cpa16(sb + so,        (const char*)g_xhi  + ga);
        cpa16(sb + A_LO + so, (const char*)g_xlo  + ga);
        cpa16(sb + B_HI + so, (const char*)g_wthi + gb);
        cpa16(sb + B_LO + so, (const char*)g_wtlo + gb);
    }
    CP_COMMIT();

    for (int c = 0; c < 8; ++c) {
        if (c < 7) {
            uint32_t nb = sb + ((c + 1) & 1)*STAGE;
            #pragma unroll
            for (int i = 0; i < 4; ++i) {
                int r = r_ + i*32;
                uint32_t so = (uint32_t)r*PITCH + (uint32_t)k16_*16;
                long ga = ((long)(row0 + r)*CC + (c+1)*64)*2 + k16_*16;
                long gb = ((long)(n0   + r)*CC + (c+1)*64)*2 + k16_*16;
                cpa16(nb + so,        (const char*)g_xhi  + ga);
                cpa16(nb + A_LO + so, (const char*)g_xlo  + ga);
                cpa16(nb + B_HI + so, (const char*)g_wthi + gb);
                cpa16(nb + B_LO + so, (const char*)g_wtlo + gb);
            }
            CP_COMMIT();
            CP_WAIT(1);
        } else {
            CP_WAIT(0);
        }
        __syncthreads();
        computeChunk(sb + (c & 1)*STAGE, wr0, wn0, lane, acc, 4);
        __syncthreads();
    }

    // tail: A = P [128x32 pad64], B = Y2t [128x32 pad64], plain stores into stage 0
    {
        uint4 z = {0,0,0,0};
        #pragma unroll
        for (int i = 0; i < 4; ++i) {
            int r = r_ + i*32;
            uint32_t so = (uint32_t)r*PITCH + (uint32_t)k16_*16;
            uint4 va = z, vb = z, vc = z, vd = z;
            if (k16_ < 4) {
                long ga = (long)(row0 + r)*64 + k16_*16;              // 32 bf16/row
                long gb = ((long)b*CC + n0 + r)*64 + k16_*16;
                va = *(const uint4*)((const char*)g_phi   + ga);
                vb = *(const uint4*)((const char*)g_plo   + ga);
                vc = *(const uint4*)((const char*)g_y2thi + gb);
                vd = *(const uint4*)((const char*)g_y2tlo + gb);
            }
            *(uint4*)(sm + so)        = va;
            *(uint4*)(sm + A_LO + so) = vb;
            *(uint4*)(sm + B_HI + so) = vc;
            *(uint4*)(sm + B_LO + so) = vd;
        }
    }
    __syncthreads();
    computeChunk(sb, wr0, wn0, lane, acc, 2);

    // epilogue: + bias, direct stores (pre-LN)
    int gr = lane >> 2, gc = (lane & 3)*2;
    #pragma unroll
    for (int mi = 0; mi < 4; ++mi)
        #pragma unroll
        for (int ni = 0; ni < 4; ++ni) {
            int col = n0 + wn0 + ni*8 + gc;
            float b0 = bias[col], b1 = bias[col+1];
            long ro0 = (long)(row0 + wr0 + mi*16 + gr)*CC + col;
            long ro1 = ro0 + 8*CC;
            float2 o0 = { acc[mi][ni][0] + b0, acc[mi][ni][1] + b1 };
            float2 o1 = { acc[mi][ni][2] + b0, acc[mi][ni][3] + b1 };
            *(float2*)(out + ro0) = o0;
            *(float2*)(out + ro1) = o1;
        }
}

// LayerNorm in-place
__global__ void __launch_bounds__(256) lnKernel(float* __restrict__ out,
                                                const float* __restrict__ gamma,
                                                const float* __restrict__ beta) {
    int tid = threadIdx.x, lane = tid & 31, wid = tid >> 5;
    long row = (long)blockIdx.x * 8 + wid;
    float4* rp = (float4*)(out + row * CC);
    float4 v[4];
    float sum = 0.f;
    #pragma unroll
    for (int j = 0; j < 4; ++j) {
        v[j] = rp[lane + j*32];
        sum += v[j].x + v[j].y + v[j].z + v[j].w;
    }
    #pragma unroll
    for (int o = 16; o; o >>= 1) sum += __shfl_xor_sync(0xffffffffu, sum, o);
    float mean = sum * (1.0f/512.0f);
    float var = 0.f;
    #pragma unroll
    for (int j = 0; j < 4; ++j) {
        float dx = v[j].x - mean, dy = v[j].y - mean, dz = v[j].z - mean, dw = v[j].w - mean;
        var += dx*dx + dy*dy + dz*dz + dw*dw;
    }
    #pragma unroll
    for (int o = 16; o; o >>= 1) var += __shfl_xor_sync(0xffffffffu, var, o);
    float rs = rsqrtf(var * (1.0f/512.0f) + 1e-5f);
    const float4* g4 = (const float4*)gamma;
    const float4* b4 = (const float4*)beta;
    #pragma unroll
    for (int j = 0; j < 4; ++j) {
        float4 g = g4[lane + j*32], bt = b4[lane + j*32];
        float4 o;
        o.x = (v[j].x - mean)*rs*g.x + bt.x;
        o.y = (v[j].y - mean)*rs*g.y + bt.y;
        o.z = (v[j].z - mean)*rs*g.z + bt.z;
        o.w = (v[j].w - mean)*rs*g.w + bt.w;
        rp[lane + j*32] = o;
    }
}

extern "C" void kernel_launch(void* const* d_in, const int* in_sizes, int n_in,
                              void* d_out, int out_size) {
    const float* x     = (const float*)d_in[0];
    const float* y     = (const float*)d_in[1];
    const float* score = (const float*)d_in[2];
    const float* W     = (const float*)d_in[3];
    const float* bias  = (const float*)d_in[4];
    const float* gamma = (const float*)d_in[5];
    const float* beta  = (const float*)d_in[6];
    float* out = (float*)d_out;

    const long OUT_ELEMS = (long)BB*NN*CC;
    int full = (out_size >= (int)(OUT_ELEMS + BB + (long)BB*NN*MM));
    float* d_ot = full ? out + OUT_ELEMS : nullptr;
    float* d_pi = full ? out + OUT_ELEMS + BB : nullptr;

    cudaFuncSetAttribute(gemmMMA, cudaFuncAttributeMaxDynamicSharedMemorySize, GSMEM);

    initKernel<<<1, 32>>>();
    nuKernel<<<BB, 256>>>(score);
    wtKernel<<<256, 256>>>(W);
    costKernel<<<512, 256>>>(x, y);
    sinkhornKernel<<<256, 256>>>();
    y2Kernel<<<64, 256>>>(y, W);
    piKernel<<<256, 256>>>(d_pi, full);
    if (full) otReduceKernel<<<1, 512>>>(d_ot);
    gemmMMA<<<2048, 256, GSMEM>>>(bias, out);
    lnKernel<<<8192, 256>>>(out, gamma, beta);
}

// round 11
// speedup vs baseline: 8.4212x; 1.2540x over previous
#include <cuda_runtime.h>
#include <cuda_bf16.h>
#include <math.h>
#include <stdint.h>

#define BB 16
#define NN 4096
#define MM 32
#define CC 512
#define MUVAL (1.0f/4096.0f)

__device__ float g_cost[BB*NN*MM];
__device__ float g_Kmat[BB*NN*MM];
__device__ float g_u[BB*NN];
__device__ float g_v[BB*MM];
__device__ float g_nu[BB*MM];
__device__ float g_sblk[2][256*MM];
__device__ float g_errblk[2][256];
__device__ float g_otpart[2048];
__device__ __align__(256) __nv_bfloat16 g_xhi[BB*NN*CC];
__device__ __align__(256) __nv_bfloat16 g_xlo[BB*NN*CC];
__device__ __align__(256) __nv_bfloat16 g_phi[BB*NN*MM];
__device__ __align__(256) __nv_bfloat16 g_plo[BB*NN*MM];
__device__ __align__(256) __nv_bfloat16 g_wthi[CC*CC];     // [n][k]
__device__ __align__(256) __nv_bfloat16 g_wtlo[CC*CC];
__device__ __align__(256) __nv_bfloat16 g_y2thi[BB*CC*MM]; // [b][n][m]
__device__ __align__(256) __nv_bfloat16 g_y2tlo[BB*CC*MM];
__device__ unsigned g_bar1[16];
__device__ unsigned g_bar2;
__device__ unsigned g_bar_gen;

__device__ __forceinline__ uint32_t smem_u32(const void* p) {
    uint32_t a;
    asm("{ .reg .u64 t; cvta.to.shared.u64 t, %1; cvt.u32.u64 %0, t; }" : "=r"(a) : "l"(p));
    return a;
}
__device__ __forceinline__ void ldsm4(uint32_t* f, uint32_t addr) {
    asm volatile("ldmatrix.sync.aligned.m8n8.x4.shared.b16 {%0,%1,%2,%3}, [%4];"
        : "=r"(f[0]), "=r"(f[1]), "=r"(f[2]), "=r"(f[3]) : "r"(addr));
}
__device__ __forceinline__ void mma16816(float* c, const uint32_t* a, const uint32_t* b) {
    asm volatile("mma.sync.aligned.m16n8k16.row.col.f32.bf16.bf16.f32 "
        "{%0,%1,%2,%3}, {%4,%5,%6,%7}, {%8,%9}, {%0,%1,%2,%3};"
        : "+f"(c[0]), "+f"(c[1]), "+f"(c[2]), "+f"(c[3])
        : "r"(a[0]), "r"(a[1]), "r"(a[2]), "r"(a[3]), "r"(b[0]), "r"(b[1]));
}
__device__ __forceinline__ void cpa16(uint32_t dst, const void* src) {
    asm volatile("cp.async.cg.shared.global [%0], [%1], 16;" :: "r"(dst), "l"(src));
}
#define CP_COMMIT() asm volatile("cp.async.commit_group;" ::: "memory")
#define CP_WAIT(n)  asm volatile("cp.async.wait_group %0;" :: "n"(n) : "memory")

__device__ __forceinline__ void split_bf16(float v, __nv_bfloat16& h, __nv_bfloat16& l) {
    h = __float2bfloat16(v);
    l = __float2bfloat16(v - __bfloat162float(h));
}

__global__ void initKernel() {
    int t = threadIdx.x;
    if (t < 16) g_bar1[t] = 0u;
    if (t == 0) { g_bar2 = 0u; g_bar_gen = 0u; }
}

__global__ void nuKernel(const float* __restrict__ score) {
    __shared__ int cnt[MM];
    int b = blockIdx.x, tid = threadIdx.x;
    if (tid < MM) cnt[tid] = 0;
    __syncthreads();
    const float* sb = score + (long)b * MM * NN;
    for (int p = tid; p < NN; p += 256) {
        float best = sb[p]; int bi = 0;
        #pragma unroll
        for (int k = 1; k < MM; ++k) {
            float v = sb[k*NN + p];
            if (v > best) { best = v; bi = k; }
        }
        atomicAdd(&cnt[bi], 1);
    }
    __syncthreads();
    if (tid < MM) {
        float t0 = (float)cnt[tid] / ((float)NN + 1e-8f) + 1e-6f;
        float s = t0;
        #pragma unroll
        for (int o = 16; o; o >>= 1) s += __shfl_xor_sync(0xffffffffu, s, o);
        g_nu[b*MM + tid] = t0 / s;
    }
}

// W1^T -> bf16 hi/lo [n][k]
__global__ void __launch_bounds__(256) wtKernel(const float* __restrict__ W) {
    __shared__ float t[32][33];
    int bx = blockIdx.x & 15, by = blockIdx.x >> 4;
    int tx = threadIdx.x & 31, ty = threadIdx.x >> 5;
    int k0 = by*32, n0 = bx*32;
    #pragma unroll
    for (int j = 0; j < 4; ++j)
        t[ty + 8*j][tx] = W[(long)(k0 + ty + 8*j)*CC + n0 + tx];
    __syncthreads();
    #pragma unroll
    for (int j = 0; j < 4; ++j) {
        int n = n0 + ty + 8*j, k = k0 + tx;
        __nv_bfloat16 h, l; split_bf16(t[tx][ty + 8*j], h, l);
        g_wthi[(long)n*CC + k] = h;
        g_wtlo[(long)n*CC + k] = l;
    }
}

// ---- fused convert(x->hi/lo) + cost/K via HMMA. 512 CTAs (16 b x 32 rowblocks) ----
#define CPCH 80
__global__ void __launch_bounds__(256) costMMA(const float* __restrict__ x,
                                               const float* __restrict__ y) {
    __shared__ __align__(16) char sXH[128*CPCH];
    __shared__ __align__(16) char sXL[128*CPCH];
    __shared__ __align__(16) char sYH[32*CPCH];
    __shared__ __align__(16) char sYL[32*CPCH];
    __shared__ float yinvs[32], xinvs[128];
    uint32_t bXH = smem_u32(sXH), bXL = smem_u32(sXL);
    uint32_t bYH = smem_u32(sYH), bYL = smem_u32(sYL);
    int tid = threadIdx.x, lane = tid & 31, wid = tid >> 5;
    int b = blockIdx.x >> 5, rb = blockIdx.x & 31;
    int row0 = rb * 128;

    // y inverse norms: 8 warps x 4 m
    #pragma unroll
    for (int q = 0; q < 4; ++q) {
        int m = wid*4 + q;
        float ss = 0.f;
        #pragma unroll
        for (int j = 0; j < 16; ++j) { float vv = y[((long)b*MM + m)*CC + lane + j*32]; ss += vv*vv; }
        #pragma unroll
        for (int o = 16; o; o >>= 1) ss += __shfl_xor_sync(0xffffffffu, ss, o);
        if (lane == 0) yinvs[m] = rsqrtf(ss);
    }

    float acc[4][4];
    #pragma unroll
    for (int i = 0; i < 4; ++i)
        #pragma unroll
        for (int j = 0; j < 4; ++j) acc[i][j] = 0.f;
    float xn = 0.f;
    int r_ = tid >> 1, kq = tid & 1;   // thread: row r_, 16 k's

    for (int kc = 0; kc < CC; kc += 32) {
        __syncthreads();
        {
            long base = ((long)(b*NN + row0 + r_))*CC + kc + kq*16;
            const float4* xp = (const float4*)(x + base);
            #pragma unroll
            for (int j = 0; j < 4; ++j) {
                float4 v = xp[j];
                xn += v.x*v.x + v.y*v.y + v.z*v.z + v.w*v.w;
                __nv_bfloat16 h0,l0,h1,l1,h2,l2,h3,l3;
                split_bf16(v.x,h0,l0); split_bf16(v.y,h1,l1);
                split_bf16(v.z,h2,l2); split_bf16(v.w,h3,l3);
                __nv_bfloat162 hp0 = __halves2bfloat162(h0,h1), hp1 = __halves2bfloat162(h2,h3);
                __nv_bfloat162 lp0 = __halves2bfloat162(l0,l1), lp1 = __halves2bfloat162(l2,l3);
                long gidx = base + j*4;
                ((__nv_bfloat162*)(g_xhi + gidx))[0] = hp0; ((__nv_bfloat162*)(g_xhi + gidx))[1] = hp1;
                ((__nv_bfloat162*)(g_xlo + gidx))[0] = lp0; ((__nv_bfloat162*)(g_xlo + gidx))[1] = lp1;
                int so = r_*CPCH + kq*32 + j*8;
                *(__nv_bfloat162*)(sXH + so) = hp0; *(__nv_bfloat162*)(sXH + so + 4) = hp1;
                *(__nv_bfloat162*)(sXL + so) = lp0; *(__nv_bfloat162*)(sXL + so + 4) = lp1;
            }
        }
        {
            int m = tid >> 3, k4 = (tid & 7) * 4;
            float4 v = *(const float4*)(y + ((long)b*MM + m)*CC + kc + k4);
            __nv_bfloat16 h0,l0,h1,l1,h2,l2,h3,l3;
            split_bf16(v.x,h0,l0); split_bf16(v.y,h1,l1);
            split_bf16(v.z,h2,l2); split_bf16(v.w,h3,l3);
            int so = m*CPCH + k4*2;
            *(__nv_bfloat162*)(sYH + so)     = __halves2bfloat162(h0,h1);
            *(__nv_bfloat162*)(sYH + so + 4) = __halves2bfloat162(h2,h3);
            *(__nv_bfloat162*)(sYL + so)     = __halves2bfloat162(l0,l1);
            *(__nv_bfloat162*)(sYL + so + 4) = __halves2bfloat162(l2,l3);
        }
        __syncthreads();
        #pragma unroll
        for (int ks = 0; ks < 2; ++ks) {
            uint32_t ah[4], al[4], bh[2][4], bl[2][4];
            uint32_t aoff = (uint32_t)(wid*16 + (lane & 15))*CPCH + (uint32_t)(ks*16 + ((lane >> 4) << 3))*2;
            ldsm4(ah, bXH + aoff);
            ldsm4(al, bXL + aoff);
            #pragma unroll
            for (int p = 0; p < 2; ++p) {
                int row = p*16 + (lane & 7) + ((lane >> 4) & 1)*8;
                int col = ks*16 + (lane & 8);
                uint32_t boff = (uint32_t)row*CPCH + (uint32_t)col*2;
                ldsm4(bh[p], bYH + boff);
                ldsm4(bl[p], bYL + boff);
            }
            #pragma unroll
            for (int ni = 0; ni < 4; ++ni) {
                const uint32_t* bhp = &bh[ni >> 1][(ni & 1)*2];
                const uint32_t* blp = &bl[ni >> 1][(ni & 1)*2];
                mma16816(acc[ni], ah, bhp);
                mma16816(acc[ni], ah, blp);
                mma16816(acc[ni], al, bhp);
            }
        }
    }
    // finalize x norms (threads 2r,2r+1 adjacent lanes)
    float xn2 = xn + __shfl_xor_sync(0xffffffffu, xn, 1);
    if ((tid & 1) == 0) xinvs[r_] = rsqrtf(xn2);
    __syncthreads();

    int gr = lane >> 2, gc = (lane & 3)*2;
    #pragma unroll
    for (int ni = 0; ni < 4; ++ni) {
        int m = ni*8 + gc;
        float ym0 = yinvs[m], ym1 = yinvs[m+1];
        #pragma unroll
        for (int h = 0; h < 2; ++h) {
            int r = wid*16 + gr + h*8;
            float xi = xinvs[r];
            float c0 = 1.f - acc[ni][h*2+0]*xi*ym0;
            float c1 = 1.f - acc[ni][h*2+1]*xi*ym1;
            long idx = ((long)(b*NN + row0 + r))*MM + m;
            *(float2*)(g_cost + idx) = make_float2(c0, c1);
            *(float2*)(g_Kmat + idx) = make_float2(expf(-c0*20.f), expf(-c1*20.f));
        }
    }
}

// sinkhorn: 256 persistent blocks, one tree barrier per iteration
__device__ __forceinline__ void gbar() {
    __threadfence();
    __syncthreads();
    if (threadIdx.x == 0) {
        unsigned my = *(volatile unsigned*)&g_bar_gen;
        unsigned a = atomicAdd(&g_bar1[blockIdx.x >> 4], 1u) + 1u;
        if ((a & 15u) == 0u) {
            unsigned b2 = atomicAdd(&g_bar2, 1u) + 1u;
            if ((b2 & 15u) == 0u) atomicAdd(&g_bar_gen, 1u);
        }
        while (*(volatile unsigned*)&g_bar_gen == my) __nanosleep(32);
        __threadfence();
    }
    __syncthreads();
}

__global__ void __launch_bounds__(256) sinkhornKernel() {
    __shared__ float ks[8*32*33];
    __shared__ float wacc[8][32];
    __shared__ float werr[8];
    int tid = threadIdx.x, lane = tid & 31, wid = tid >> 5;
    int blk = blockIdx.x, gw = blk*8 + wid;
    int b = gw >> 7, chunk = gw & 127;
    long rowbase = (long)b*NN + chunk*32;
    float* kw = ks + wid*(32*33);
    for (int r = 0; r < 32; ++r)
        kw[r*33 + lane] = g_Kmat[(rowbase + r)*MM + lane];
    __syncwarp();
    float uprev = 0.f, vreg = 0.f;
    for (int it = 0; it < 50; ++it) {
        int buf = it & 1;
        float s = 0.f;
        #pragma unroll
        for (int m = 0; m < 32; ++m)
            s += kw[lane*33 + m] * __shfl_sync(0xffffffffu, vreg, m);
        float un = MUVAL / (s + 1e-8f);
        float errl = fabsf(un - uprev);
        uprev = un;
        float acc = 0.f;
        #pragma unroll
        for (int j = 0; j < 32; ++j)
            acc += kw[j*33 + lane] * __shfl_sync(0xffffffffu, un, j);
        #pragma unroll
        for (int o = 16; o; o >>= 1) errl += __shfl_xor_sync(0xffffffffu, errl, o);
        wacc[wid][lane] = acc;
        if (lane == 0) werr[wid] = errl;
        __syncthreads();
        if (wid == 0) {
            float ba = wacc[0][lane]+wacc[1][lane]+wacc[2][lane]+wacc[3][lane]
                     + wacc[4][lane]+wacc[5][lane]+wacc[6][lane]+wacc[7][lane];
            __stcg(&g_sblk[buf][blk*32 + lane], ba);
            if (lane == 0)
                __stcg(&g_errblk[buf][blk],
                       werr[0]+werr[1]+werr[2]+werr[3]+werr[4]+werr[5]+werr[6]+werr[7]);
        }
        gbar();
        float ss = 0.f;
        #pragma unroll
        for (int j = 0; j < 16; ++j)
            ss += __ldcg(&g_sblk[buf][(b*16 + j)*32 + lane]);
        vreg = g_nu[b*MM + lane] / (ss + 1e-8f);
        float e = 0.f;
        #pragma unroll
        for (int j = 0; j < 8; ++j)
            e += __ldcg(&g_errblk[buf][lane + 32*j]);
        #pragma unroll
        for (int o = 16; o; o >>= 1) e += __shfl_xor_sync(0xffffffffu, e, o);
        if (e * (1.0f/16.0f) < 0.1f) break;
    }
    g_u[rowbase + lane] = uprev;
    if (chunk == 0) g_v[b*MM + lane] = vreg;
}

// Y2^T -> bf16 hi/lo [b][n][m]
__global__ void __launch_bounds__(256) y2Kernel(const float* __restrict__ y,
                                                const float* __restrict__ W) {
    __shared__ float ys[MM][64];
    int tid = threadIdx.x;
    int b = blockIdx.x >> 2, c0 = (blockIdx.x & 3) * 128;
    int col = c0 + (tid & 127), mh = tid >> 7;
    const float* W2 = W + 512*512;
    float acc[16];
    #pragma unroll
    for (int i = 0; i < 16; ++i) acc[i] = 0.f;
    for (int kc = 0; kc < CC; kc += 64) {
        __syncthreads();
        {
            int m = tid >> 3, k4 = (tid & 7) * 8;
            *(float4*)&ys[m][k4]     = *(const float4*)(y + ((long)b*MM + m)*CC + kc + k4);
            *(float4*)&ys[m][k4 + 4] = *(const float4*)(y + ((long)b*MM + m)*CC + kc + k4 + 4);
        }
        __syncthreads();
        #pragma unroll 4
        for (int k = 0; k < 64; ++k) {
            float w = W2[(long)(kc + k)*CC + col];
            #pragma unroll
            for (int i = 0; i < 16; ++i) acc[i] += ys[mh*16 + i][k] * w;
        }
    }
    #pragma unroll
    for (int i = 0; i < 16; ++i) {
        __nv_bfloat16 h, l; split_bf16(acc[i], h, l);
        long idx = ((long)b*CC + col)*MM + mh*16 + i;
        g_y2thi[idx] = h;
        g_y2tlo[idx] = l;
    }
}

__global__ void __launch_bounds__(256) piKernel(float* __restrict__ d_pi, int write_pi) {
    int tid = threadIdx.x, lane = tid & 31, wid = tid >> 5;
    int gw = blockIdx.x * 8 + wid;
    int b = gw >> 7, sub = gw & 127;
    float vv = g_v[b*MM + lane];
    float ot = 0.f;
    for (int r = 0; r < 32; ++r) {
        int n = sub*32 + r;
        long idx = ((long)b*NN + n) * MM + lane;
        float pi = g_u[b*NN + n] * g_Kmat[idx] * vv;
        float rs = pi;
        #pragma unroll
        for (int o = 16; o; o >>= 1) rs += __shfl_xor_sync(0xffffffffu, rs, o);
        float pn = pi / (rs + 1e-8f);
        __nv_bfloat16 h, l; split_bf16(pn, h, l);
        g_phi[idx] = h; g_plo[idx] = l;
        if (write_pi) d_pi[idx] = pi;
        ot += pi * g_cost[idx];
    }
    #pragma unroll
    for (int o = 16; o; o >>= 1) ot += __shfl_xor_sync(0xffffffffu, ot, o);
    if (lane == 0) g_otpart[gw] = ot;
}

__global__ void otReduceKernel(float* __restrict__ d_ot) {
    int lane = threadIdx.x & 31, b = threadIdx.x >> 5;
    float s = g_otpart[b*128 + lane] + g_otpart[b*128 + lane + 32]
            + g_otpart[b*128 + lane + 64] + g_otpart[b*128 + lane + 96];
    #pragma unroll
    for (int o = 16; o; o >>= 1) s += __shfl_xor_sync(0xffffffffu, s, o);
    if (lane == 0) d_ot[b] = s;
}

// ---- HMMA GEMM, K=32 chunks, 2 stages (2 CTAs/SM). 2048 CTAs ----
#define GP 80
#define GA_LO 10240
#define GB_HI 20480
#define GB_LO 30720
#define GSTAGE 40960
#define GSMEM (2*GSTAGE)

__device__ __forceinline__ void gemmCompute(uint32_t sbase, int wr0, int wn0, int lane,
                                            float acc[4][4][4]) {
    #pragma unroll
    for (int ks = 0; ks < 2; ++ks) {
        uint32_t ah[4][4], al[4][4];
        #pragma unroll
        for (int mi = 0; mi < 4; ++mi) {
            uint32_t aoff = (uint32_t)(wr0 + mi*16 + (lane & 15))*GP + (uint32_t)(ks*16 + ((lane >> 4) << 3))*2;
            ldsm4(ah[mi], sbase + aoff);
            ldsm4(al[mi], sbase + GA_LO + aoff);
        }
        uint32_t bh[2][4], bl[2][4];
        #pragma unroll
        for (int p = 0; p < 2; ++p) {
            int row = wn0 + p*16 + (lane & 7) + ((lane >> 4) & 1)*8;
            int col = ks*16 + (lane & 8);
            uint32_t boff = (uint32_t)row*GP + (uint32_t)col*2;
            ldsm4(bh[p], sbase + GB_HI + boff);
            ldsm4(bl[p], sbase + GB_LO + boff);
        }
        #pragma unroll
        for (int mi = 0; mi < 4; ++mi)
            #pragma unroll
            for (int ni = 0; ni < 4; ++ni) {
                const uint32_t* bhp = &bh[ni >> 1][(ni & 1)*2];
                const uint32_t* blp = &bl[ni >> 1][(ni & 1)*2];
                mma16816(acc[mi][ni], ah[mi], bhp);
                mma16816(acc[mi][ni], ah[mi], blp);
                mma16816(acc[mi][ni], al[mi], bhp);
            }
    }
}

__global__ void __launch_bounds__(256, 2) gemmMMA(const float* __restrict__ bias,
                                                  float* __restrict__ out) {
    extern __shared__ char sm[];
    uint32_t sb = smem_u32(sm);
    int tid = threadIdx.x, lane = tid & 31, wid = tid >> 5;
    int rowTile = blockIdx.x >> 2, colTile = blockIdx.x & 3;
    int row0 = rowTile*128, n0 = colTile*128;
    int b = rowTile >> 5;
    int wr0 = (wid >> 2)*64, wn0 = (wid & 3)*32;

    float acc[4][4][4];
    #pragma unroll
    for (int i = 0; i < 4; ++i)
        #pragma unroll
        for (int j = 0; j < 4; ++j)
            #pragma unroll
            for (int q = 0; q < 4; ++q) acc[i][j][q] = 0.f;

    int r_ = tid >> 2, k16_ = tid & 3;

    // chunk c loader: c in [0,16) = X/W at kc=c*32; c==16 = tail P/Y2 (exactly 32 k)
    auto loadChunk = [&](int c, uint32_t dst) {
        #pragma unroll
        for (int i = 0; i < 2; ++i) {
            int u = tid + i*256, r = u >> 2, k16 = u & 3;
            uint32_t so = (uint32_t)r*GP + (uint32_t)k16*16;
            if (c < 16) {
                long ga = ((long)(row0 + r)*CC + c*32)*2 + k16*16;
                long gb = ((long)(n0   + r)*CC + c*32)*2 + k16*16;
                cpa16(dst + so,         (const char*)g_xhi  + ga);
                cpa16(dst + GA_LO + so, (const char*)g_xlo  + ga);
                cpa16(dst + GB_HI + so, (const char*)g_wthi + gb);
                cpa16(dst + GB_LO + so, (const char*)g_wtlo + gb);
            } else {
                long ga = (long)(row0 + r)*64 + k16*16;
                long gb = ((long)b*CC + n0 + r)*64 + k16*16;
                cpa16(dst + so,         (const char*)g_phi   + ga);
                cpa16(dst + GA_LO + so, (const char*)g_plo   + ga);
                cpa16(dst + GB_HI + so, (const char*)g_y2thi + gb);
                cpa16(dst + GB_LO + so, (const char*)g_y2tlo + gb);
            }
        }
        CP_COMMIT();
    };
    (void)r_; (void)k16_;

    loadChunk(0, sb);
    for (int c = 0; c < 17; ++c) {
        if (c < 16) {
            loadChunk(c + 1, sb + ((c + 1) & 1)*GSTAGE);
            CP_WAIT(1);
        } else {
            CP_WAIT(0);
        }
        __syncthreads();
        gemmCompute(sb + (c & 1)*GSTAGE, wr0, wn0, lane, acc);
        __syncthreads();
    }

    int gr = lane >> 2, gc = (lane & 3)*2;
    #pragma unroll
    for (int mi = 0; mi < 4; ++mi)
        #pragma unroll
        for (int ni = 0; ni < 4; ++ni) {
            int col = n0 + wn0 + ni*8 + gc;
            float b0 = bias[col], b1 = bias[col+1];
            long ro0 = (long)(row0 + wr0 + mi*16 + gr)*CC + col;
            long ro1 = ro0 + 8*CC;
            float2 o0 = { acc[mi][ni][0] + b0, acc[mi][ni][1] + b1 };
            float2 o1 = { acc[mi][ni][2] + b0, acc[mi][ni][3] + b1 };
            *(float2*)(out + ro0) = o0;
            *(float2*)(out + ro1) = o1;
        }
}

// LayerNorm in-place
__global__ void __launch_bounds__(256) lnKernel(float* __restrict__ out,
                                                const float* __restrict__ gamma,
                                                const float* __restrict__ beta) {
    int tid = threadIdx.x, lane = tid & 31, wid = tid >> 5;
    long row = (long)blockIdx.x * 8 + wid;
    float4* rp = (float4*)(out + row * CC);
    float4 v[4];
    float sum = 0.f;
    #pragma unroll
    for (int j = 0; j < 4; ++j) {
        v[j] = rp[lane + j*32];
        sum += v[j].x + v[j].y + v[j].z + v[j].w;
    }
    #pragma unroll
    for (int o = 16; o; o >>= 1) sum += __shfl_xor_sync(0xffffffffu, sum, o);
    float mean = sum * (1.0f/512.0f);
    float var = 0.f;
    #pragma unroll
    for (int j = 0; j < 4; ++j) {
        float dx = v[j].x - mean, dy = v[j].y - mean, dz = v[j].z - mean, dw = v[j].w - mean;
        var += dx*dx + dy*dy + dz*dz + dw*dw;
    }
    #pragma unroll
    for (int o = 16; o; o >>= 1) var += __shfl_xor_sync(0xffffffffu, var, o);
    float rs = rsqrtf(var * (1.0f/512.0f) + 1e-5f);
    const float4* g4 = (const float4*)gamma;
    const float4* b4 = (const float4*)beta;
    #pragma unroll
    for (int j = 0; j < 4; ++j) {
        float4 g = g4[lane + j*32], bt = b4[lane + j*32];
        float4 o;
        o.x = (v[j].x - mean)*rs*g.x + bt.x;
        o.y = (v[j].y - mean)*rs*g.y + bt.y;
        o.z = (v[j].z - mean)*rs*g.z + bt.z;
        o.w = (v[j].w - mean)*rs*g.w + bt.w;
        rp[lane + j*32] = o;
    }
}

extern "C" void kernel_launch(void* const* d_in, const int* in_sizes, int n_in,
                              void* d_out, int out_size) {
    const float* x     = (const float*)d_in[0];
    const float* y     = (const float*)d_in[1];
    const float* score = (const float*)d_in[2];
    const float* W     = (const float*)d_in[3];
    const float* bias  = (const float*)d_in[4];
    const float* gamma = (const float*)d_in[5];
    const float* beta  = (const float*)d_in[6];
    float* out = (float*)d_out;

    const long OUT_ELEMS = (long)BB*NN*CC;
    int full = (out_size >= (int)(OUT_ELEMS + BB + (long)BB*NN*MM));
    float* d_ot = full ? out + OUT_ELEMS : nullptr;
    float* d_pi = full ? out + OUT_ELEMS + BB : nullptr;

    static cudaStream_t s2 = 0;
    static cudaEvent_t evRoot = 0, evNu = 0, evSide = 0;
    if (!s2) {
        cudaStreamCreateWithFlags(&s2, cudaStreamNonBlocking);
        cudaEventCreateWithFlags(&evRoot, cudaEventDisableTiming);
        cudaEventCreateWithFlags(&evNu, cudaEventDisableTiming);
        cudaEventCreateWithFlags(&evSide, cudaEventDisableTiming);
        cudaFuncSetAttribute(gemmMMA, cudaFuncAttributeMaxDynamicSharedMemorySize, GSMEM);
    }

    cudaEventRecord(evRoot, 0);
    cudaStreamWaitEvent(s2, evRoot, 0);
    nuKernel<<<BB, 256, 0, s2>>>(score);
    cudaEventRecord(evNu, s2);
    wtKernel<<<256, 256, 0, s2>>>(W);
    y2Kernel<<<64, 256, 0, s2>>>(y, W);
    cudaEventRecord(evSide, s2);

    initKernel<<<1, 32>>>();
    costMMA<<<512, 256>>>(x, y);
    cudaStreamWaitEvent(0, evNu, 0);
    sinkhornKernel<<<256, 256>>>();
    piKernel<<<256, 256>>>(d_pi, full);
    if (full) otReduceKernel<<<1, 512>>>(d_ot);
    cudaStreamWaitEvent(0, evSide, 0);
    gemmMMA<<<2048, 256, GSMEM>>>(bias, out);
    lnKernel<<<8192, 256>>>(out, gamma, beta);
}

// round 12
// speedup vs baseline: 9.1894x; 1.0912x over previous
#include <cuda_runtime.h>
#include <cuda_bf16.h>
#include <math.h>
#include <stdint.h>

#define BB 16
#define NN 4096
#define MM 32
#define CC 512
#define MUVAL (1.0f/4096.0f)

__device__ float g_Kmat[BB*NN*MM];
__device__ float g_nu[BB*MM];
__device__ float g_sblk[2][256*MM];
__device__ float g_errblk2[2][4][256];
__device__ float g_otpart[2048];
__device__ __align__(256) __nv_bfloat16 g_xhi[BB*NN*CC];
__device__ __align__(256) __nv_bfloat16 g_xlo[BB*NN*CC];
__device__ __align__(256) __nv_bfloat16 g_phi[BB*NN*MM];
__device__ __align__(256) __nv_bfloat16 g_plo[BB*NN*MM];
__device__ __align__(256) __nv_bfloat16 g_wthi[CC*CC];     // [n][k]
__device__ __align__(256) __nv_bfloat16 g_wtlo[CC*CC];
__device__ __align__(256) __nv_bfloat16 g_y2thi[BB*CC*MM]; // [b][n][m]
__device__ __align__(256) __nv_bfloat16 g_y2tlo[BB*CC*MM];
__device__ unsigned g_bar1[16];
__device__ unsigned g_bar2;
__device__ unsigned g_bar_gen;
__device__ unsigned g_bbar[16];
__device__ unsigned g_bgen[16];

__device__ __forceinline__ uint32_t smem_u32(const void* p) {
    uint32_t a;
    asm("{ .reg .u64 t; cvta.to.shared.u64 t, %1; cvt.u32.u64 %0, t; }" : "=r"(a) : "l"(p));
    return a;
}
__device__ __forceinline__ void ldsm4(uint32_t* f, uint32_t addr) {
    asm volatile("ldmatrix.sync.aligned.m8n8.x4.shared.b16 {%0,%1,%2,%3}, [%4];"
        : "=r"(f[0]), "=r"(f[1]), "=r"(f[2]), "=r"(f[3]) : "r"(addr));
}
__device__ __forceinline__ void mma16816(float* c, const uint32_t* a, const uint32_t* b) {
    asm volatile("mma.sync.aligned.m16n8k16.row.col.f32.bf16.bf16.f32 "
        "{%0,%1,%2,%3}, {%4,%5,%6,%7}, {%8,%9}, {%0,%1,%2,%3};"
        : "+f"(c[0]), "+f"(c[1]), "+f"(c[2]), "+f"(c[3])
        : "r"(a[0]), "r"(a[1]), "r"(a[2]), "r"(a[3]), "r"(b[0]), "r"(b[1]));
}
__device__ __forceinline__ void cpa16(uint32_t dst, const void* src) {
    asm volatile("cp.async.cg.shared.global [%0], [%1], 16;" :: "r"(dst), "l"(src));
}
#define CP_COMMIT() asm volatile("cp.async.commit_group;" ::: "memory")
#define CP_WAIT(n)  asm volatile("cp.async.wait_group %0;" :: "n"(n) : "memory")

__device__ __forceinline__ void split_bf16(float v, __nv_bfloat16& h, __nv_bfloat16& l) {
    h = __float2bfloat16(v);
    l = __float2bfloat16(v - __bfloat162float(h));
}

__global__ void initKernel() {
    int t = threadIdx.x;
    if (t < 16) { g_bar1[t] = 0u; g_bbar[t] = 0u; g_bgen[t] = 0u; }
    if (t == 0) { g_bar2 = 0u; g_bar_gen = 0u; }
}

__global__ void nuKernel(const float* __restrict__ score) {
    __shared__ int cnt[MM];
    int b = blockIdx.x, tid = threadIdx.x;
    if (tid < MM) cnt[tid] = 0;
    __syncthreads();
    const float* sb = score + (long)b * MM * NN;
    for (int p = tid; p < NN; p += 256) {
        float best = sb[p]; int bi = 0;
        #pragma unroll
        for (int k = 1; k < MM; ++k) {
            float v = sb[k*NN + p];
            if (v > best) { best = v; bi = k; }
        }
        atomicAdd(&cnt[bi], 1);
    }
    __syncthreads();
    if (tid < MM) {
        float t0 = (float)cnt[tid] / ((float)NN + 1e-8f) + 1e-6f;
        float s = t0;
        #pragma unroll
        for (int o = 16; o; o >>= 1) s += __shfl_xor_sync(0xffffffffu, s, o);
        g_nu[b*MM + tid] = t0 / s;
    }
}

// W1^T -> bf16 hi/lo [n][k]
__global__ void __launch_bounds__(256) wtKernel(const float* __restrict__ W) {
    __shared__ float t[32][33];
    int bx = blockIdx.x & 15, by = blockIdx.x >> 4;
    int tx = threadIdx.x & 31, ty = threadIdx.x >> 5;
    int k0 = by*32, n0 = bx*32;
    #pragma unroll
    for (int j = 0; j < 4; ++j)
        t[ty + 8*j][tx] = W[(long)(k0 + ty + 8*j)*CC + n0 + tx];
    __syncthreads();
    #pragma unroll
    for (int j = 0; j < 4; ++j) {
        int n = n0 + ty + 8*j, k = k0 + tx;
        __nv_bfloat16 h, l; split_bf16(t[tx][ty + 8*j], h, l);
        g_wthi[(long)n*CC + k] = h;
        g_wtlo[(long)n*CC + k] = l;
    }
}

// ---- fused convert(x->hi/lo) + K via HMMA. 512 CTAs (16 b x 32 rowblocks) ----
#define CPCH 80
__global__ void __launch_bounds__(256) costMMA(const float* __restrict__ x,
                                               const float* __restrict__ y) {
    __shared__ __align__(16) char sXH[128*CPCH];
    __shared__ __align__(16) char sXL[128*CPCH];
    __shared__ __align__(16) char sYH[32*CPCH];
    __shared__ __align__(16) char sYL[32*CPCH];
    __shared__ float yinvs[32], xinvs[128];
    uint32_t bXH = smem_u32(sXH), bXL = smem_u32(sXL);
    uint32_t bYH = smem_u32(sYH), bYL = smem_u32(sYL);
    int tid = threadIdx.x, lane = tid & 31, wid = tid >> 5;
    int b = blockIdx.x >> 5, rb = blockIdx.x & 31;
    int row0 = rb * 128;

    #pragma unroll
    for (int q = 0; q < 4; ++q) {
        int m = wid*4 + q;
        float ss = 0.f;
        #pragma unroll
        for (int j = 0; j < 16; ++j) { float vv = y[((long)b*MM + m)*CC + lane + j*32]; ss += vv*vv; }
        #pragma unroll
        for (int o = 16; o; o >>= 1) ss += __shfl_xor_sync(0xffffffffu, ss, o);
        if (lane == 0) yinvs[m] = rsqrtf(ss);
    }

    float acc[4][4];
    #pragma unroll
    for (int i = 0; i < 4; ++i)
        #pragma unroll
        for (int j = 0; j < 4; ++j) acc[i][j] = 0.f;
    float xn = 0.f;
    int r_ = tid >> 1, kq = tid & 1;

    for (int kc = 0; kc < CC; kc += 32) {
        __syncthreads();
        {
            long base = ((long)(b*NN + row0 + r_))*CC + kc + kq*16;
            const float4* xp = (const float4*)(x + base);
            #pragma unroll
            for (int j = 0; j < 4; ++j) {
                float4 v = xp[j];
                xn += v.x*v.x + v.y*v.y + v.z*v.z + v.w*v.w;
                __nv_bfloat16 h0,l0,h1,l1,h2,l2,h3,l3;
                split_bf16(v.x,h0,l0); split_bf16(v.y,h1,l1);
                split_bf16(v.z,h2,l2); split_bf16(v.w,h3,l3);
                __nv_bfloat162 hp0 = __halves2bfloat162(h0,h1), hp1 = __halves2bfloat162(h2,h3);
                __nv_bfloat162 lp0 = __halves2bfloat162(l0,l1), lp1 = __halves2bfloat162(l2,l3);
                long gidx = base + j*4;
                ((__nv_bfloat162*)(g_xhi + gidx))[0] = hp0; ((__nv_bfloat162*)(g_xhi + gidx))[1] = hp1;
                ((__nv_bfloat162*)(g_xlo + gidx))[0] = lp0; ((__nv_bfloat162*)(g_xlo + gidx))[1] = lp1;
                int so = r_*CPCH + kq*32 + j*8;
                *(__nv_bfloat162*)(sXH + so) = hp0; *(__nv_bfloat162*)(sXH + so + 4) = hp1;
                *(__nv_bfloat162*)(sXL + so) = lp0; *(__nv_bfloat162*)(sXL + so + 4) = lp1;
            }
        }
        {
            int m = tid >> 3, k4 = (tid & 7) * 4;
            float4 v = *(const float4*)(y + ((long)b*MM + m)*CC + kc + k4);
            __nv_bfloat16 h0,l0,h1,l1,h2,l2,h3,l3;
            split_bf16(v.x,h0,l0); split_bf16(v.y,h1,l1);
            split_bf16(v.z,h2,l2); split_bf16(v.w,h3,l3);
            int so = m*CPCH + k4*2;
            *(__nv_bfloat162*)(sYH + so)     = __halves2bfloat162(h0,h1);
            *(__nv_bfloat162*)(sYH + so + 4) = __halves2bfloat162(h2,h3);
            *(__nv_bfloat162*)(sYL + so)     = __halves2bfloat162(l0,l1);
            *(__nv_bfloat162*)(sYL + so + 4) = __halves2bfloat162(l2,l3);
        }
        __syncthreads();
        #pragma unroll
        for (int ks = 0; ks < 2; ++ks) {
            uint32_t ah[4], al[4], bh[2][4], bl[2][4];
            uint32_t aoff = (uint32_t)(wid*16 + (lane & 15))*CPCH + (uint32_t)(ks*16 + ((lane >> 4) << 3))*2;
            ldsm4(ah, bXH + aoff);
            ldsm4(al, bXL + aoff);
            #pragma unroll
            for (int p = 0; p < 2; ++p) {
                int row = p*16 + (lane & 7) + ((lane >> 4) & 1)*8;
                int col = ks*16 + (lane & 8);
                uint32_t boff = (uint32_t)row*CPCH + (uint32_t)col*2;
                ldsm4(bh[p], bYH + boff);
                ldsm4(bl[p], bYL + boff);
            }
            #pragma unroll
            for (int ni = 0; ni < 4; ++ni) {
                const uint32_t* bhp = &bh[ni >> 1][(ni & 1)*2];
                const uint32_t* blp = &bl[ni >> 1][(ni & 1)*2];
                mma16816(acc[ni], ah, bhp);
                mma16816(acc[ni], ah, blp);
                mma16816(acc[ni], al, bhp);
            }
        }
    }
    float xn2 = xn + __shfl_xor_sync(0xffffffffu, xn, 1);
    if ((tid & 1) == 0) xinvs[r_] = rsqrtf(xn2);
    __syncthreads();

    int gr = lane >> 2, gc = (lane & 3)*2;
    #pragma unroll
    for (int ni = 0; ni < 4; ++ni) {
        int m = ni*8 + gc;
        float ym0 = yinvs[m], ym1 = yinvs[m+1];
        #pragma unroll
        for (int h = 0; h < 2; ++h) {
            int r = wid*16 + gr + h*8;
            float xi = xinvs[r];
            float c0 = 1.f - acc[ni][h*2+0]*xi*ym0;
            float c1 = 1.f - acc[ni][h*2+1]*xi*ym1;
            long idx = ((long)(b*NN + row0 + r))*MM + m;
            *(float2*)(g_Kmat + idx) = make_float2(expf(-c0*20.f), expf(-c1*20.f));
        }
    }
}

// ---- sinkhorn: per-batch barrier per iter, global err check every 4 iters; pi fused ----
__device__ __forceinline__ void gbar() {
    __threadfence();
    __syncthreads();
    if (threadIdx.x == 0) {
        unsigned my = *(volatile unsigned*)&g_bar_gen;
        unsigned a = atomicAdd(&g_bar1[blockIdx.x >> 4], 1u) + 1u;
        if ((a & 15u) == 0u) {
            unsigned b2 = atomicAdd(&g_bar2, 1u) + 1u;
            if ((b2 & 15u) == 0u) atomicAdd(&g_bar_gen, 1u);
        }
        while (*(volatile unsigned*)&g_bar_gen == my) __nanosleep(32);
        __threadfence();
    }
    __syncthreads();
}
__device__ __forceinline__ void bbar(int batch) {
    __threadfence();
    __syncthreads();
    if (threadIdx.x == 0) {
        unsigned my = *(volatile unsigned*)&g_bgen[batch];
        if (atomicAdd(&g_bbar[batch], 1u) == 15u) {
            atomicExch(&g_bbar[batch], 0u);
            __threadfence();
            atomicAdd(&g_bgen[batch], 1u);
        } else {
            while (*(volatile unsigned*)&g_bgen[batch] == my) __nanosleep(32);
        }
        __threadfence();
    }
    __syncthreads();
}

__global__ void __launch_bounds__(256) sinkhornKernel(float* __restrict__ d_pi, int write_pi) {
    __shared__ float ks[8*32*33];
    __shared__ float wacc[8][32];
    __shared__ float werr[8];
    __shared__ float dec[4];
    int tid = threadIdx.x, lane = tid & 31, wid = tid >> 5;
    int blk = blockIdx.x, gw = blk*8 + wid;
    int b = gw >> 7, chunk = gw & 127;
    long rowbase = (long)b*NN + chunk*32;
    float* kw = ks + wid*(32*33);
    for (int r = 0; r < 32; ++r)
        kw[r*33 + lane] = g_Kmat[(rowbase + r)*MM + lane];
    __syncwarp();

    float uprev = 0.f, vreg = 0.f;
    float usnap[4], vsnap[4];
    int done = 0;

    for (int g = 0; g < 13 && !done; ++g) {
        int len = (g == 12) ? 2 : 4;
        #pragma unroll
        for (int j = 0; j < 4; ++j) {
            if (j >= len) break;
            int it = g*4 + j;
            int buf = it & 1;
            float s = 0.f;
            #pragma unroll
            for (int m = 0; m < 32; ++m)
                s += kw[lane*33 + m] * __shfl_sync(0xffffffffu, vreg, m);
            float un = MUVAL / (s + 1e-8f);
            float errl = fabsf(un - uprev);
            uprev = un;
            float acc = 0.f;
            #pragma unroll
            for (int jj = 0; jj < 32; ++jj)
                acc += kw[jj*33 + lane] * __shfl_sync(0xffffffffu, un, jj);
            #pragma unroll
            for (int o = 16; o; o >>= 1) errl += __shfl_xor_sync(0xffffffffu, errl, o);
            wacc[wid][lane] = acc;
            if (lane == 0) werr[wid] = errl;
            __syncthreads();
            if (wid == 0) {
                float ba = wacc[0][lane]+wacc[1][lane]+wacc[2][lane]+wacc[3][lane]
                         + wacc[4][lane]+wacc[5][lane]+wacc[6][lane]+wacc[7][lane];
                __stcg(&g_sblk[buf][blk*32 + lane], ba);
                if (lane == 0)
                    __stcg(&g_errblk2[g & 1][j][blk],
                           werr[0]+werr[1]+werr[2]+werr[3]+werr[4]+werr[5]+werr[6]+werr[7]);
            }
            bbar(b);
            float ss = 0.f;
            #pragma unroll
            for (int q = 0; q < 16; ++q)
                ss += __ldcg(&g_sblk[buf][(b*16 + q)*32 + lane]);
            vreg = g_nu[b*MM + lane] / (ss + 1e-8f);
            usnap[j] = uprev;
            vsnap[j] = vreg;
        }
        gbar();
        if (tid < 4) dec[tid] = 1e30f;
        __syncthreads();
        if (wid < len) {
            float e = 0.f;
            #pragma unroll
            for (int q = 0; q < 8; ++q)
                e += __ldcg(&g_errblk2[g & 1][wid][lane + 32*q]);
            #pragma unroll
            for (int o = 16; o; o >>= 1) e += __shfl_xor_sync(0xffffffffu, e, o);
            if (lane == 0) dec[wid] = e;
        }
        __syncthreads();
        #pragma unroll
        for (int j = 0; j < 4; ++j) {
            if (!done && dec[j] < 1.6f) {
                uprev = usnap[j];
                vreg = vsnap[j];
                done = 1;
            }
        }
    }

    // fused pi / pinorm / ot epilogue (K in smem, u/v in regs)
    float ot = 0.f;
    for (int r = 0; r < 32; ++r) {
        float ur = __shfl_sync(0xffffffffu, uprev, r);
        float Kx = kw[r*33 + lane];
        float pi = ur * Kx * vreg;
        float rs = pi;
        #pragma unroll
        for (int o = 16; o; o >>= 1) rs += __shfl_xor_sync(0xffffffffu, rs, o);
        float pn = pi / (rs + 1e-8f);
        __nv_bfloat16 h, l; split_bf16(pn, h, l);
        long idx = (rowbase + r)*MM + lane;
        g_phi[idx] = h; g_plo[idx] = l;
        if (write_pi) d_pi[idx] = pi;
        ot += pi * (-logf(Kx) * 0.05f);
    }
    #pragma unroll
    for (int o = 16; o; o >>= 1) ot += __shfl_xor_sync(0xffffffffu, ot, o);
    if (lane == 0) g_otpart[gw] = ot;
}

// Y2^T -> bf16 hi/lo [b][n][m]
__global__ void __launch_bounds__(256) y2Kernel(const float* __restrict__ y,
                                                const float* __restrict__ W) {
    __shared__ float ys[MM][64];
    int tid = threadIdx.x;
    int b = blockIdx.x >> 2, c0 = (blockIdx.x & 3) * 128;
    int col = c0 + (tid & 127), mh = tid >> 7;
    const float* W2 = W + 512*512;
    float acc[16];
    #pragma unroll
    for (int i = 0; i < 16; ++i) acc[i] = 0.f;
    for (int kc = 0; kc < CC; kc += 64) {
        __syncthreads();
        {
            int m = tid >> 3, k4 = (tid & 7) * 8;
            *(float4*)&ys[m][k4]     = *(const float4*)(y + ((long)b*MM + m)*CC + kc + k4);
            *(float4*)&ys[m][k4 + 4] = *(const float4*)(y + ((long)b*MM + m)*CC + kc + k4 + 4);
        }
        __syncthreads();
        #pragma unroll 4
        for (int k = 0; k < 64; ++k) {
            float w = W2[(long)(kc + k)*CC + col];
            #pragma unroll
            for (int i = 0; i < 16; ++i) acc[i] += ys[mh*16 + i][k] * w;
        }
    }
    #pragma unroll
    for (int i = 0; i < 16; ++i) {
        __nv_bfloat16 h, l; split_bf16(acc[i], h, l);
        long idx = ((long)b*CC + col)*MM + mh*16 + i;
        g_y2thi[idx] = h;
        g_y2tlo[idx] = l;
    }
}

__global__ void otReduceKernel(float* __restrict__ d_ot) {
    int lane = threadIdx.x & 31, b = threadIdx.x >> 5;
    float s = g_otpart[b*128 + lane] + g_otpart[b*128 + lane + 32]
            + g_otpart[b*128 + lane + 64] + g_otpart[b*128 + lane + 96];
    #pragma unroll
    for (int o = 16; o; o >>= 1) s += __shfl_xor_sync(0xffffffffu, s, o);
    if (lane == 0) d_ot[b] = s;
}

// ---- HMMA GEMM, K=32 chunks, 2 stages (2 CTAs/SM). 2048 CTAs ----
#define GP 80
#define GA_LO 10240
#define GB_HI 20480
#define GB_LO 30720
#define GSTAGE 40960
#define GSMEM (2*GSTAGE)

__device__ __forceinline__ void gemmCompute(uint32_t sbase, int wr0, int wn0, int lane,
                                            float acc[4][4][4]) {
    #pragma unroll
    for (int ks = 0; ks < 2; ++ks) {
        uint32_t ah[4][4], al[4][4];
        #pragma unroll
        for (int mi = 0; mi < 4; ++mi) {
            uint32_t aoff = (uint32_t)(wr0 + mi*16 + (lane & 15))*GP + (uint32_t)(ks*16 + ((lane >> 4) << 3))*2;
            ldsm4(ah[mi], sbase + aoff);
            ldsm4(al[mi], sbase + GA_LO + aoff);
        }
        uint32_t bh[2][4], bl[2][4];
        #pragma unroll
        for (int p = 0; p < 2; ++p) {
            int row = wn0 + p*16 + (lane & 7) + ((lane >> 4) & 1)*8;
            int col = ks*16 + (lane & 8);
            uint32_t boff = (uint32_t)row*GP + (uint32_t)col*2;
            ldsm4(bh[p], sbase + GB_HI + boff);
            ldsm4(bl[p], sbase + GB_LO + boff);
        }
        #pragma unroll
        for (int mi = 0; mi < 4; ++mi)
            #pragma unroll
            for (int ni = 0; ni < 4; ++ni) {
                const uint32_t* bhp = &bh[ni >> 1][(ni & 1)*2];
                const uint32_t* blp = &bl[ni >> 1][(ni & 1)*2];
                mma16816(acc[mi][ni], ah[mi], bhp);
                mma16816(acc[mi][ni], ah[mi], blp);
                mma16816(acc[mi][ni], al[mi], bhp);
            }
    }
}

__global__ void __launch_bounds__(256, 2) gemmMMA(const float* __restrict__ bias,
                                                  float* __restrict__ out) {
    extern __shared__ char sm[];
    uint32_t sb = smem_u32(sm);
    int tid = threadIdx.x, lane = tid & 31, wid = tid >> 5;
    int rowTile = blockIdx.x >> 2, colTile = blockIdx.x & 3;
    int row0 = rowTile*128, n0 = colTile*128;
    int b = rowTile >> 5;
    int wr0 = (wid >> 2)*64, wn0 = (wid & 3)*32;

    float acc[4][4][4];
    #pragma unroll
    for (int i = 0; i < 4; ++i)
        #pragma unroll
        for (int j = 0; j < 4; ++j)
            #pragma unroll
            for (int q = 0; q < 4; ++q) acc[i][j][q] = 0.f;

    auto loadChunk = [&](int c, uint32_t dst) {
        #pragma unroll
        for (int i = 0; i < 2; ++i) {
            int u = tid + i*256, r = u >> 2, k16 = u & 3;
            uint32_t so = (uint32_t)r*GP + (uint32_t)k16*16;
            if (c < 16) {
                long ga = ((long)(row0 + r)*CC + c*32)*2 + k16*16;
                long gb = ((long)(n0   + r)*CC + c*32)*2 + k16*16;
                cpa16(dst + so,         (const char*)g_xhi  + ga);
                cpa16(dst + GA_LO + so, (const char*)g_xlo  + ga);
                cpa16(dst + GB_HI + so, (const char*)g_wthi + gb);
                cpa16(dst + GB_LO + so, (const char*)g_wtlo + gb);
            } else {
                long ga = (long)(row0 + r)*64 + k16*16;
                long gb = ((long)b*CC + n0 + r)*64 + k16*16;
                cpa16(dst + so,         (const char*)g_phi   + ga);
                cpa16(dst + GA_LO + so, (const char*)g_plo   + ga);
                cpa16(dst + GB_HI + so, (const char*)g_y2thi + gb);
                cpa16(dst + GB_LO + so, (const char*)g_y2tlo + gb);
            }
        }
        CP_COMMIT();
    };

    loadChunk(0, sb);
    for (int c = 0; c < 17; ++c) {
        if (c < 16) {
            loadChunk(c + 1, sb + ((c + 1) & 1)*GSTAGE);
            CP_WAIT(1);
        } else {
            CP_WAIT(0);
        }
        __syncthreads();
        gemmCompute(sb + (c & 1)*GSTAGE, wr0, wn0, lane, acc);
        __syncthreads();
    }

    int gr = lane >> 2, gc = (lane & 3)*2;
    #pragma unroll
    for (int mi = 0; mi < 4; ++mi)
        #pragma unroll
        for (int ni = 0; ni < 4; ++ni) {
            int col = n0 + wn0 + ni*8 + gc;
            float b0 = bias[col], b1 = bias[col+1];
            long ro0 = (long)(row0 + wr0 + mi*16 + gr)*CC + col;
            long ro1 = ro0 + 8*CC;
            float2 o0 = { acc[mi][ni][0] + b0, acc[mi][ni][1] + b1 };
            float2 o1 = { acc[mi][ni][2] + b0, acc[mi][ni][3] + b1 };
            *(float2*)(out + ro0) = o0;
            *(float2*)(out + ro1) = o1;
        }
}

// LayerNorm in-place
__global__ void __launch_bounds__(256) lnKernel(float* __restrict__ out,
                                                const float* __restrict__ gamma,
                                                const float* __restrict__ beta) {
    int tid = threadIdx.x, lane = tid & 31, wid = tid >> 5;
    long row = (long)blockIdx.x * 8 + wid;
    float4* rp = (float4*)(out + row * CC);
    float4 v[4];
    float sum = 0.f;
    #pragma unroll
    for (int j = 0; j < 4; ++j) {
        v[j] = rp[lane + j*32];
        sum += v[j].x + v[j].y + v[j].z + v[j].w;
    }
    #pragma unroll
    for (int o = 16; o; o >>= 1) sum += __shfl_xor_sync(0xffffffffu, sum, o);
    float mean = sum * (1.0f/512.0f);
    float var = 0.f;
    #pragma unroll
    for (int j = 0; j < 4; ++j) {
        float dx = v[j].x - mean, dy = v[j].y - mean, dz = v[j].z - mean, dw = v[j].w - mean;
        var += dx*dx + dy*dy + dz*dz + dw*dw;
    }
    #pragma unroll
    for (int o = 16; o; o >>= 1) var += __shfl_xor_sync(0xffffffffu, var, o);
    float rs = rsqrtf(var * (1.0f/512.0f) + 1e-5f);
    const float4* g4 = (const float4*)gamma;
    const float4* b4 = (const float4*)beta;
    #pragma unroll
    for (int j = 0; j < 4; ++j) {
        float4 g = g4[lane + j*32], bt = b4[lane + j*32];
        float4 o;
        o.x = (v[j].x - mean)*rs*g.x + bt.x;
        o.y = (v[j].y - mean)*rs*g.y + bt.y;
        o.z = (v[j].z - mean)*rs*g.z + bt.z;
        o.w = (v[j].w - mean)*rs*g.w + bt.w;
        rp[lane + j*32] = o;
    }
}

extern "C" void kernel_launch(void* const* d_in, const int* in_sizes, int n_in,
                              void* d_out, int out_size) {
    const float* x     = (const float*)d_in[0];
    const float* y     = (const float*)d_in[1];
    const float* score = (const float*)d_in[2];
    const float* W     = (const float*)d_in[3];
    const float* bias  = (const float*)d_in[4];
    const float* gamma = (const float*)d_in[5];
    const float* beta  = (const float*)d_in[6];
    float* out = (float*)d_out;

    const long OUT_ELEMS = (long)BB*NN*CC;
    int full = (out_size >= (int)(OUT_ELEMS + BB + (long)BB*NN*MM));
    float* d_ot = full ? out + OUT_ELEMS : nullptr;
    float* d_pi = full ? out + OUT_ELEMS + BB : nullptr;

    static cudaStream_t s2 = 0;
    static cudaEvent_t evRoot = 0, evNu = 0, evSide = 0;
    if (!s2) {
        cudaStreamCreateWithFlags(&s2, cudaStreamNonBlocking);
        cudaEventCreateWithFlags(&evRoot, cudaEventDisableTiming);
        cudaEventCreateWithFlags(&evNu, cudaEventDisableTiming);
        cudaEventCreateWithFlags(&evSide, cudaEventDisableTiming);
        cudaFuncSetAttribute(gemmMMA, cudaFuncAttributeMaxDynamicSharedMemorySize, GSMEM);
    }

    cudaEventRecord(evRoot, 0);
    cudaStreamWaitEvent(s2, evRoot, 0);
    nuKernel<<<BB, 256, 0, s2>>>(score);
    cudaEventRecord(evNu, s2);
    wtKernel<<<256, 256, 0, s2>>>(W);
    y2Kernel<<<64, 256, 0, s2>>>(y, W);
    cudaEventRecord(evSide, s2);

    initKernel<<<1, 32>>>();
    costMMA<<<512, 256>>>(x, y);
    cudaStreamWaitEvent(0, evNu, 0);
    sinkhornKernel<<<256, 256>>>(d_pi, full);
    if (full) otReduceKernel<<<1, 512>>>(d_ot);
    cudaStreamWaitEvent(0, evSide, 0);
    gemmMMA<<<2048, 256, GSMEM>>>(bias, out);
    lnKernel<<<8192, 256>>>(out, gamma, beta);
}